// round 4
// baseline (speedup 1.0000x reference)
#include <cuda_runtime.h>
#include <cuda_fp16.h>
#include <math.h>

namespace {
constexpr int H    = 16;
constexpr int C    = 32;
constexpr int HID  = 512;
constexpr int SKUD = 64;
constexpr int ROWS = 32;     // batch rows per CTA
constexpr int NTHR = 256;
constexpr int XTS  = 36;     // X^T row stride in floats (144B: 16B-aligned rows)
constexpr int BSTR = 520;    // beta row stride in halves (even)

constexpr float TEMP_INV = 1.0f / 0.7f;
constexpr float TMAX     = 365.0f;
constexpr float LN_EPS   = 1e-3f;

// shared layout (floats)
constexpr int OFF_XT   = 0;                         // X^T / sku^T / H1^T : 512*36
constexpr int OFF_BETA = OFF_XT + 512 * XTS;        // fp16 beta: 32*520 halves = 8320 floats
constexpr int OFF_PSH0 = OFF_BETA + ROWS * BSTR/2;  // 8*33
constexpr int OFF_PSH1 = OFF_PSH0 + 8 * 33;         // 8*33
constexpr int OFF_GMAX = OFF_PSH1 + 8 * 33;         // 32
constexpr int OFF_WAWO = OFF_GMAX + 32;             // 64
constexpr int SMEM_FLOATS = OFF_WAWO + SKUD;
constexpr int SMEM_BYTES  = SMEM_FLOATS * 4;        // ~109.5 KB -> 2 CTAs/SM
}

using ull = unsigned long long;

__device__ __forceinline__ ull pack2(float x, float y) {
    ull r; asm("mov.b64 %0, {%1, %2};" : "=l"(r) : "f"(x), "f"(y)); return r;
}
__device__ __forceinline__ float2 unpack2(ull v) {
    float2 f; asm("mov.b64 {%0, %1}, %2;" : "=f"(f.x), "=f"(f.y) : "l"(v)); return f;
}
__device__ __forceinline__ void ffma2(ull& d, ull a, ull b) {
    asm("fma.rn.f32x2 %0, %1, %2, %0;" : "+l"(d) : "l"(a), "l"(b));
}
__device__ __forceinline__ float mishf(float x) {
    float sp = (x > 20.f) ? x : log1pf(expf(x));
    return x * tanhf(sp);
}

// Column-major GEMM: thread owns output cols (c0, c0+1) for all 32 rows.
// acc0[p] = f32x2 of rows (2p,2p+1) col c0; acc1[p] same for col c0+1.
// W streamed from global (coalesced LDG.64, L2-resident), X^T broadcast from shared.
// NO barriers inside.
__device__ __forceinline__ void gemm_col(
    const float* __restrict__ gW, int ktot,
    const float* __restrict__ sXT, int c0,
    ull acc0[16], ull acc1[16])
{
#pragma unroll
    for (int p = 0; p < 16; p++) { acc0[p] = 0ull; acc1[p] = 0ull; }

    float2 w = *reinterpret_cast<const float2*>(gW + c0);
#pragma unroll 2
    for (int k = 0; k < ktot; k++) {
        float2 wn = w;
        if (k + 1 < ktot)
            wn = *reinterpret_cast<const float2*>(gW + (size_t)(k + 1) * HID + c0);
        ull w0 = pack2(w.x, w.x);
        ull w1 = pack2(w.y, w.y);
        const float* xr = sXT + (size_t)k * XTS;
#pragma unroll
        for (int q = 0; q < 8; q++) {
            ulonglong2 xq = *reinterpret_cast<const ulonglong2*>(xr + 4 * q); // rows 4q..4q+3 (broadcast)
            ffma2(acc0[2 * q],     xq.x, w0);
            ffma2(acc0[2 * q + 1], xq.y, w0);
            ffma2(acc1[2 * q],     xq.x, w1);
            ffma2(acc1[2 * q + 1], xq.y, w1);
        }
        w = wn;
    }
}

__global__ __launch_bounds__(NTHR, 2)
void holiday_fused_kernel(
    const float* __restrict__ inputs,     // [B,16]
    const float* __restrict__ sku,        // [B,64]
    const float* __restrict__ deltas,     // [16,32]
    const float* __restrict__ ln_gamma,   // [16,32]
    const float* __restrict__ ln_beta,    // [16,32]
    const float* __restrict__ attn_w,     // [16]
    const float* __restrict__ Wh,         // [16,32,32]
    const float* __restrict__ Wah,        // [512,512]
    const float* __restrict__ Waa,        // [512,512]
    const float* __restrict__ Wb,         // [64,512]
    const float* __restrict__ Wa,         // [64,512]
    const float* __restrict__ Wo,         // [512,1]
    float* __restrict__ out)              // [B]
{
    extern __shared__ float sm[];
    float*  sXT    = sm + OFF_XT;
    __half* sBetaH = reinterpret_cast<__half*>(sm + OFF_BETA);
    float*  psh0   = sm + OFF_PSH0;
    float*  psh1   = sm + OFF_PSH1;
    float*  gmaxA  = sm + OFF_GMAX;
    float*  sWaWo  = sm + OFF_WAWO;

    const int tid = threadIdx.x;
    const int tx  = tid & 31;
    const int wid = tid >> 5;
    const int c0  = 2 * tid;            // this thread's 2 output columns
    const int c1  = c0 + 1;
    const int b0  = blockIdx.x * ROWS;
    const unsigned FULL = 0xffffffffu;

    // ---- prologue: WaWo[s] = Wa[s,:].Wo (alpha folded through final dot) ----
#pragma unroll
    for (int si = 0; si < SKUD / 8; si++) {
        int s = wid * 8 + si;
        float p = 0.f;
#pragma unroll
        for (int j = 0; j < 16; j++) {
            int c = tx + 32 * j;
            p = fmaf(__ldg(Wa + s * HID + c), __ldg(Wo + c), p);
        }
#pragma unroll
        for (int o = 16; o > 0; o >>= 1) p += __shfl_xor_sync(FULL, p, o);
        if (tx == 0) sWaWo[s] = p;
    }

    // ---- changepoints via warp shuffle-scan (registers only) ---------------
    float cps_r[2];
#pragma unroll
    for (int tt = 0; tt < 2; tt++) {
        int h = wid + 8 * tt;
        float d  = deltas[h * C + tx];
        float sp = (d > 20.f) ? d : log1pf(expf(d));
        float s  = sp;
#pragma unroll
        for (int o = 1; o < 32; o <<= 1) {
            float v = __shfl_up_sync(FULL, s, o);
            if (tx >= o) s += v;
        }
        float tot = __shfl_sync(FULL, s, 31);
        cps_r[tt] = s * (TMAX / tot);
    }

    // ---- stage sku^T into the X^T region (rows 0..63) ----------------------
    {
        int r  = tid >> 3;            // 0..31
        int k0 = (tid & 7) * 8;       // 0..56
        const float4* s4 = reinterpret_cast<const float4*>(sku + (size_t)(b0 + r) * SKUD + k0);
        float4 a = s4[0], b = s4[1];
        sXT[(k0 + 0) * XTS + r] = a.x;  sXT[(k0 + 1) * XTS + r] = a.y;
        sXT[(k0 + 2) * XTS + r] = a.z;  sXT[(k0 + 3) * XTS + r] = a.w;
        sXT[(k0 + 4) * XTS + r] = b.x;  sXT[(k0 + 5) * XTS + r] = b.y;
        sXT[(k0 + 6) * XTS + r] = b.z;  sXT[(k0 + 7) * XTS + r] = b.w;
    }
    __syncthreads();

    ull acc0[16], acc1[16];

    // ---- GEMM0: beta = sigmoid(sku @ Wb) -> fp16 shared --------------------
    gemm_col(Wb, SKUD, sXT, c0, acc0, acc1);
#pragma unroll
    for (int p = 0; p < 16; p++) {
        float2 a = unpack2(acc0[p]);   // rows 2p,2p+1 @ col c0
        float2 b = unpack2(acc1[p]);   // rows 2p,2p+1 @ col c1
        float s00 = 1.0f / (1.0f + expf(-a.x)), s10 = 1.0f / (1.0f + expf(-b.x));
        float s01 = 1.0f / (1.0f + expf(-a.y)), s11 = 1.0f / (1.0f + expf(-b.y));
        *reinterpret_cast<__half2*>(sBetaH + (2 * p)     * BSTR + c0) = __floats2half2_rn(s00, s10);
        *reinterpret_cast<__half2*>(sBetaH + (2 * p + 1) * BSTR + c0) = __floats2half2_rn(s01, s11);
    }
    __syncthreads();   // sku^T reads done -> stage1 may overwrite X^T

    // ---- stage 1: per-(row,holiday) features -> X^T ------------------------
#pragma unroll
    for (int tt = 0; tt < 2; tt++) {
        int h = wid + 8 * tt;          // warp-uniform
        float t = inputs[(size_t)(b0 + tx) * H + h];
        float f[C], e[C];
        float mu = 0.f;
#pragma unroll
        for (int c = 0; c < C; c++) {
            float cp = __shfl_sync(FULL, cps_r[tt], c);
            f[c] = fmaxf(t - cp, 0.f); mu += f[c];
        }
        mu *= (1.0f / C);
        float var = 0.f;
#pragma unroll
        for (int c = 0; c < C; c++) { float d = f[c] - mu; var = fmaf(d, d, var); }
        var *= (1.0f / C);
        float rs = rsqrtf(var + LN_EPS);
        float aw = __ldg(attn_w + h) * TEMP_INV;
        float m = -3.4e38f;
#pragma unroll
        for (int c = 0; c < C; c++) {
            float n = fmaf((f[c] - mu) * rs, __ldg(ln_gamma + h * C + c),
                           __ldg(ln_beta + h * C + c));
            f[c] = n;
            m = fmaxf(m, n * aw);
        }
        float s = 0.f;
#pragma unroll
        for (int c = 0; c < C; c++) { e[c] = expf(f[c] * aw - m); s += e[c]; }
        float inv = 1.0f / s;

        ull hid2[16];
#pragma unroll
        for (int d = 0; d < 16; d++) hid2[d] = 0ull;
#pragma unroll
        for (int c = 0; c < C; c++) {
            float a = f[c] * e[c] * inv;
            ull a2 = pack2(a, a);
            const ull* wr = reinterpret_cast<const ull*>(Wh + (h * C + c) * C);
#pragma unroll
            for (int d = 0; d < 16; d++) ffma2(hid2[d], a2, wr[d]);
        }
#pragma unroll
        for (int d = 0; d < 16; d++) {
            float2 hv = unpack2(hid2[d]);
            sXT[(h * 32 + 2 * d)     * XTS + tx] = mishf(hv.x);
            sXT[(h * 32 + 2 * d + 1) * XTS + tx] = mishf(hv.y);
        }
    }
    __syncthreads();   // X^T ready

    // ---- GEMM1: H1 = mish(X @ Wah) -----------------------------------------
    gemm_col(Wah, HID, sXT, c0, acc0, acc1);
    __syncthreads();   // all X^T reads done
#pragma unroll
    for (int p = 0; p < 16; p++) {
        float2 a = unpack2(acc0[p]);
        float2 b = unpack2(acc1[p]);
        *reinterpret_cast<ull*>(sXT + (size_t)c0 * XTS + 2 * p) = pack2(mishf(a.x), mishf(a.y));
        *reinterpret_cast<ull*>(sXT + (size_t)c1 * XTS + 2 * p) = pack2(mishf(b.x), mishf(b.y));
    }
    __syncthreads();   // H1^T ready

    // ---- GEMM2: logits = H1 @ Waa  (stays in registers) --------------------
    gemm_col(Waa, HID, sXT, c0, acc0, acc1);

    // ---- epilogue ----------------------------------------------------------
    // (1) per-row max over this thread's 2 cols, warp butterfly, cross-warp
    {
        float vm[32];
#pragma unroll
        for (int p = 0; p < 16; p++) {
            float2 l0 = unpack2(acc0[p]);
            float2 l1 = unpack2(acc1[p]);
            vm[2 * p]     = fmaxf(l0.x, l1.x);
            vm[2 * p + 1] = fmaxf(l0.y, l1.y);
        }
        float mine = 0.f;
#pragma unroll
        for (int r = 0; r < 32; r++) {
            float v = vm[r];
#pragma unroll
            for (int o = 16; o > 0; o >>= 1) v = fmaxf(v, __shfl_xor_sync(FULL, v, o));
            if (tx == r) mine = v;
        }
        psh0[wid * 33 + tx] = mine;
    }
    __syncthreads();
    if (tid < 32) {
        float m = -3.4e38f;
#pragma unroll
        for (int w = 0; w < 8; w++) m = fmaxf(m, psh0[w * 33 + tid]);
        gmaxA[tid] = m;
    }
    __syncthreads();

    // (2) exp-sum partials
    {
        float vs[32];
#pragma unroll
        for (int p = 0; p < 16; p++) {
            float2 l0 = unpack2(acc0[p]);
            float2 l1 = unpack2(acc1[p]);
            int r = 2 * p;
            vs[r]     = expf((l0.x - gmaxA[r])     * TEMP_INV) + expf((l1.x - gmaxA[r])     * TEMP_INV);
            vs[r + 1] = expf((l0.y - gmaxA[r + 1]) * TEMP_INV) + expf((l1.y - gmaxA[r + 1]) * TEMP_INV);
        }
        float mine = 0.f;
#pragma unroll
        for (int r = 0; r < 32; r++) {
            float v = vs[r];
#pragma unroll
            for (int o = 16; o > 0; o >>= 1) v += __shfl_xor_sync(FULL, v, o);
            if (tx == r) mine = v;
        }
        psh0[wid * 33 + tx] = mine;   // safe: prior psh0 consumers passed the barrier
    }

    // (3) weighted-dot partials: e * H1 * beta * Wo over this thread's 2 cols
    {
        float2 wo = *reinterpret_cast<const float2*>(Wo + c0);
        float pr[32];
#pragma unroll
        for (int p = 0; p < 16; p++) {
            float2 l0 = unpack2(acc0[p]);
            float2 l1 = unpack2(acc1[p]);
#pragma unroll
            for (int rr = 0; rr < 2; rr++) {
                int r = 2 * p + rr;
                float la = rr ? l0.y : l0.x;
                float lb = rr ? l1.y : l1.x;
                float gm = gmaxA[r];
                float e0 = expf((la - gm) * TEMP_INV);
                float e1 = expf((lb - gm) * TEMP_INV);
                float h10 = sXT[(size_t)c0 * XTS + r];
                float h11 = sXT[(size_t)c1 * XTS + r];
                float2 bf = __half22float2(
                    *reinterpret_cast<const __half2*>(sBetaH + r * BSTR + c0));
                pr[r] = e0 * h10 * bf.x * wo.x + e1 * h11 * bf.y * wo.y;
            }
        }
        float mine = 0.f;
#pragma unroll
        for (int r = 0; r < 32; r++) {
            float v = pr[r];
#pragma unroll
            for (int o = 16; o > 0; o >>= 1) v += __shfl_xor_sync(FULL, v, o);
            if (tx == r) mine = v;
        }
        psh1[wid * 33 + tx] = mine;
    }
    __syncthreads();

    // (4) finishers: combine warps, apply 1/sum, add alpha, write out
    if (tid < 32) {
        int row = tid;
        float gs = 0.f, tot = 0.f;
#pragma unroll
        for (int w = 0; w < 8; w++) { gs += psh0[w * 33 + row]; tot += psh1[w * 33 + row]; }
        float alpha = 0.f;
        const float4* sk4 = reinterpret_cast<const float4*>(sku + (size_t)(b0 + row) * SKUD);
#pragma unroll
        for (int s4i = 0; s4i < 16; s4i++) {
            float4 sv = sk4[s4i];
            alpha += sv.x * sWaWo[4 * s4i]     + sv.y * sWaWo[4 * s4i + 1]
                   + sv.z * sWaWo[4 * s4i + 2] + sv.w * sWaWo[4 * s4i + 3];
        }
        out[b0 + row] = tot / gs + alpha;
    }
}

extern "C" void kernel_launch(void* const* d_in, const int* in_sizes, int n_in,
                              void* d_out, int out_size)
{
    const float* inputs   = (const float*)d_in[0];
    const float* sku      = (const float*)d_in[1];
    const float* deltas   = (const float*)d_in[2];
    const float* ln_gamma = (const float*)d_in[3];
    const float* ln_beta  = (const float*)d_in[4];
    const float* attn_w   = (const float*)d_in[5];
    const float* Wh       = (const float*)d_in[6];
    const float* Wah      = (const float*)d_in[7];
    const float* Waa      = (const float*)d_in[8];
    const float* Wb       = (const float*)d_in[9];
    const float* Wa       = (const float*)d_in[10];
    const float* Wo       = (const float*)d_in[11];
    float* out = (float*)d_out;

    int B = in_sizes[0] / H;
    cudaFuncSetAttribute(holiday_fused_kernel,
                         cudaFuncAttributeMaxDynamicSharedMemorySize, SMEM_BYTES);
    holiday_fused_kernel<<<B / ROWS, NTHR, SMEM_BYTES>>>(
        inputs, sku, deltas, ln_gamma, ln_beta, attn_w,
        Wh, Wah, Waa, Wb, Wa, Wo, out);
}

// round 6
// speedup vs baseline: 1.6885x; 1.6885x over previous
#include <cuda_runtime.h>
#include <cuda_fp16.h>
#include <math.h>

namespace {
constexpr int H    = 16;
constexpr int C    = 32;
constexpr int HID  = 512;
constexpr int SKUD = 64;
constexpr int ROWS = 32;
constexpr int NTHR = 256;
constexpr int KT   = 8;
constexpr int XTS  = 36;     // X^T row stride (floats), 16B-aligned rows

constexpr float TEMP_INV = 1.0f / 0.7f;
constexpr float TMAX     = 365.0f;
constexpr float LN_EPS   = 1e-3f;

// shared layout (floats)
constexpr int OFF_XT   = 0;                    // 512*36 = 18432 (sku^T / X^T / H1^T)
constexpr int OFF_WT   = OFF_XT + 512 * XTS;   // 8*512 = 4096 (W k-tile)
constexpr int OFF_WO   = OFF_WT + KT * HID;    // 512
constexpr int OFF_PS0  = OFF_WO + HID;         // 8*9 = 72
constexpr int OFF_PS1  = OFF_PS0 + 72;         // 72
constexpr int OFF_GMAX = OFF_PS1 + 72;         // 32
constexpr int OFF_WAWO = OFF_GMAX + 32;        // 64
constexpr int SMEM_FLOATS = OFF_WAWO + SKUD;   // 23280
constexpr int SMEM_BYTES  = SMEM_FLOATS * 4;   // 93120 B -> 2 CTAs/SM
}

using ull = unsigned long long;

__device__ __forceinline__ ull pack2(float x, float y) {
    ull r; asm("mov.b64 %0, {%1, %2};" : "=l"(r) : "f"(x), "f"(y)); return r;
}
__device__ __forceinline__ float2 unpack2(ull v) {
    float2 f; asm("mov.b64 {%0, %1}, %2;" : "=f"(f.x), "=f"(f.y) : "l"(v)); return f;
}
__device__ __forceinline__ void ffma2(ull& d, ull a, ull b) {
    asm("fma.rn.f32x2 %0, %1, %2, %0;" : "+l"(d) : "l"(a), "l"(b));
}
__device__ __forceinline__ float mishf(float x) {
    float sp = (x > 20.f) ? x : log1pf(expf(x));
    return x * tanhf(sp);
}

// 8 rows x 8 cols per thread. acc[i][j] = f32x2 over cols (cj, cj+1) for row r0+i,
// cj = wcol + 64*j. W staged through shared in KT tiles (unrolled kk, immediate
// offsets). X^T rows broadcast via LDS.128. Contains __syncthreads: all call.
__device__ __forceinline__ void gemm8x8(
    const float* __restrict__ gW, int ktot,
    const float* __restrict__ sXT, int r0, int wcol,
    float* sWt, ull acc[8][4], int tid)
{
#pragma unroll
    for (int i = 0; i < 8; i++)
#pragma unroll
        for (int j = 0; j < 4; j++) acc[i][j] = 0ull;

    for (int kt = 0; kt < ktot; kt += KT) {
        __syncthreads();
        const float4* src = reinterpret_cast<const float4*>(gW + (size_t)kt * HID);
        float4*       dst = reinterpret_cast<float4*>(sWt);
#pragma unroll
        for (int i = 0; i < (KT * HID / 4) / NTHR; i++)
            dst[tid + i * NTHR] = src[tid + i * NTHR];
        __syncthreads();

        const float* xb = sXT + (size_t)kt * XTS + r0;
        const float* wb = sWt + wcol;
#pragma unroll
        for (int kk = 0; kk < KT; kk++) {
            float4 xa = *reinterpret_cast<const float4*>(xb + kk * XTS);      // rows r0..r0+3 (bcast)
            float4 xc = *reinterpret_cast<const float4*>(xb + kk * XTS + 4);  // rows r0+4..r0+7
            ull w2[4];
#pragma unroll
            for (int j = 0; j < 4; j++)
                w2[j] = *reinterpret_cast<const ull*>(wb + kk * HID + 64 * j);
            float xr[8] = {xa.x, xa.y, xa.z, xa.w, xc.x, xc.y, xc.z, xc.w};
#pragma unroll
            for (int i = 0; i < 8; i++) {
                ull xs = pack2(xr[i], xr[i]);
#pragma unroll
                for (int j = 0; j < 4; j++) ffma2(acc[i][j], xs, w2[j]);
            }
        }
    }
}

__global__ __launch_bounds__(NTHR, 2)
void holiday_fused_kernel(
    const float* __restrict__ inputs,     // [B,16]
    const float* __restrict__ sku,        // [B,64]
    const float* __restrict__ deltas,     // [16,32]
    const float* __restrict__ ln_gamma,   // [16,32]
    const float* __restrict__ ln_beta,    // [16,32]
    const float* __restrict__ attn_w,     // [16]
    const float* __restrict__ Wh,         // [16,32,32]
    const float* __restrict__ Wah,        // [512,512]
    const float* __restrict__ Waa,        // [512,512]
    const float* __restrict__ Wb,         // [64,512]
    const float* __restrict__ Wa,         // [64,512]
    const float* __restrict__ Wo,         // [512,1]
    float* __restrict__ out)              // [B]
{
    extern __shared__ float sm[];
    float* sXT   = sm + OFF_XT;
    float* sWt   = sm + OFF_WT;
    float* sWo   = sm + OFF_WO;
    float* ps0   = sm + OFF_PS0;
    float* ps1   = sm + OFF_PS1;
    float* gmaxA = sm + OFF_GMAX;
    float* sWaWo = sm + OFF_WAWO;

    const int tid  = threadIdx.x;
    const int tx   = tid & 31;
    const int wid  = tid >> 5;
    const int half = wid >> 2;          // col half (0/1): 256 cols each
    const int r0   = (wid & 3) * 8;     // this warp's 8 rows
    const int wcol = half * 256 + 2 * tx;
    const int b0   = blockIdx.x * ROWS;
    const unsigned FULL = 0xffffffffu;

    // ---- prologue: Wo -> smem; WaWo[s] = Wa[s,:].Wo (alpha fold) -----------
    for (int i = tid; i < HID; i += NTHR) sWo[i] = Wo[i];
#pragma unroll
    for (int si = 0; si < SKUD / 8; si++) {
        int s = wid * 8 + si;
        float p = 0.f;
#pragma unroll
        for (int j = 0; j < 16; j++) {
            int c = tx + 32 * j;
            p = fmaf(__ldg(Wa + s * HID + c), __ldg(Wo + c), p);
        }
#pragma unroll
        for (int o = 16; o > 0; o >>= 1) p += __shfl_xor_sync(FULL, p, o);
        if (tx == 0) sWaWo[s] = p;
    }

    // ---- changepoints via warp shuffle-scan --------------------------------
    float cps_r[2];
#pragma unroll
    for (int tt = 0; tt < 2; tt++) {
        int h = wid + 8 * tt;
        float d  = deltas[h * C + tx];
        float sp = (d > 20.f) ? d : log1pf(expf(d));
        float s  = sp;
#pragma unroll
        for (int o = 1; o < 32; o <<= 1) {
            float v = __shfl_up_sync(FULL, s, o);
            if (tx >= o) s += v;
        }
        float tot = __shfl_sync(FULL, s, 31);
        cps_r[tt] = s * (TMAX / tot);
    }

    // ---- stage sku^T into X^T rows 0..63 -----------------------------------
    {
        int r  = tid >> 3;
        int k0 = (tid & 7) * 8;
        const float4* s4 = reinterpret_cast<const float4*>(sku + (size_t)(b0 + r) * SKUD + k0);
        float4 a = s4[0], b = s4[1];
        sXT[(k0 + 0) * XTS + r] = a.x;  sXT[(k0 + 1) * XTS + r] = a.y;
        sXT[(k0 + 2) * XTS + r] = a.z;  sXT[(k0 + 3) * XTS + r] = a.w;
        sXT[(k0 + 4) * XTS + r] = b.x;  sXT[(k0 + 5) * XTS + r] = b.y;
        sXT[(k0 + 6) * XTS + r] = b.z;  sXT[(k0 + 7) * XTS + r] = b.w;
    }
    // (gemm8x8 opens with __syncthreads)

    ull acc[8][4];

    // ---- GEMM0: beta = sigmoid(sku @ Wb) -> registers (fp16x2) -------------
    gemm8x8(Wb, SKUD, sXT, r0, wcol, sWt, acc, tid);
    __half2 b2[8][4];
#pragma unroll
    for (int i = 0; i < 8; i++)
#pragma unroll
        for (int j = 0; j < 4; j++) {
            float2 v = unpack2(acc[i][j]);
            b2[i][j] = __floats2half2_rn(1.0f / (1.0f + expf(-v.x)),
                                         1.0f / (1.0f + expf(-v.y)));
        }
    __syncthreads();   // sku^T reads done -> stage1 may overwrite X^T

    // ---- stage 1: per-(row,holiday) features -> X^T ------------------------
#pragma unroll
    for (int tt = 0; tt < 2; tt++) {
        int h = wid + 8 * tt;          // warp-uniform
        float t = inputs[(size_t)(b0 + tx) * H + h];
        float f[C], e[C];
        float mu = 0.f;
#pragma unroll
        for (int c = 0; c < C; c++) {
            float cp = __shfl_sync(FULL, cps_r[tt], c);
            f[c] = fmaxf(t - cp, 0.f); mu += f[c];
        }
        mu *= (1.0f / C);
        float var = 0.f;
#pragma unroll
        for (int c = 0; c < C; c++) { float d = f[c] - mu; var = fmaf(d, d, var); }
        var *= (1.0f / C);
        float rs = rsqrtf(var + LN_EPS);
        float aw = __ldg(attn_w + h) * TEMP_INV;
        float m = -3.4e38f;
#pragma unroll
        for (int c = 0; c < C; c++) {
            float n = fmaf((f[c] - mu) * rs, __ldg(ln_gamma + h * C + c),
                           __ldg(ln_beta + h * C + c));
            f[c] = n;
            m = fmaxf(m, n * aw);
        }
        float s = 0.f;
#pragma unroll
        for (int c = 0; c < C; c++) { e[c] = expf(f[c] * aw - m); s += e[c]; }
        float inv = 1.0f / s;

        ull hid2[16];
#pragma unroll
        for (int d = 0; d < 16; d++) hid2[d] = 0ull;
#pragma unroll
        for (int c = 0; c < C; c++) {
            float a = f[c] * e[c] * inv;
            ull a2 = pack2(a, a);
            const ull* wr = reinterpret_cast<const ull*>(Wh + (h * C + c) * C);
#pragma unroll
            for (int d = 0; d < 16; d++) ffma2(hid2[d], a2, wr[d]);
        }
#pragma unroll
        for (int d = 0; d < 16; d++) {
            float2 hv = unpack2(hid2[d]);
            sXT[(h * 32 + 2 * d)     * XTS + tx] = mishf(hv.x);
            sXT[(h * 32 + 2 * d + 1) * XTS + tx] = mishf(hv.y);
        }
    }
    // (gemm8x8 opens with __syncthreads -> X^T visible)

    // ---- GEMM1: H1 = mish(X @ Wah) -----------------------------------------
    gemm8x8(Wah, HID, sXT, r0, wcol, sWt, acc, tid);
    __syncthreads();   // all X^T reads done; overwrite with H1^T
#pragma unroll
    for (int i = 0; i < 8; i++)
#pragma unroll
        for (int j = 0; j < 4; j++) {
            float2 v = unpack2(acc[i][j]);
            int cj = wcol + 64 * j;
            sXT[(size_t)cj       * XTS + r0 + i] = mishf(v.x);
            sXT[(size_t)(cj + 1) * XTS + r0 + i] = mishf(v.y);
        }
    // (gemm8x8 opens with __syncthreads -> H1^T visible)

    // ---- GEMM2: logits = H1 @ Waa (stays in registers) ---------------------
    gemm8x8(Waa, HID, sXT, r0, wcol, sWt, acc, tid);

    // ---- epilogue ----------------------------------------------------------
    // (1) row max
#pragma unroll
    for (int i = 0; i < 8; i++) {
        float m = -3.4e38f;
#pragma unroll
        for (int j = 0; j < 4; j++) {
            float2 l = unpack2(acc[i][j]);
            m = fmaxf(m, fmaxf(l.x, l.y));
        }
#pragma unroll
        for (int o = 16; o > 0; o >>= 1) m = fmaxf(m, __shfl_xor_sync(FULL, m, o));
        if (tx == 0) ps0[wid * 9 + i] = m;
    }
    __syncthreads();
    if (tid < 32) {
        int r = tid, w1 = r >> 3;
        gmaxA[r] = fmaxf(ps0[w1 * 9 + (r & 7)], ps0[(w1 + 4) * 9 + (r & 7)]);
    }
    __syncthreads();

    // (2) exp-sum + weighted dot (e * H1 * beta * Wo), per row
#pragma unroll
    for (int i = 0; i < 8; i++) {
        int r = r0 + i;
        float gm = gmaxA[r];
        float s = 0.f, d = 0.f;
#pragma unroll
        for (int j = 0; j < 4; j++) {
            int cj = wcol + 64 * j;
            float2 l  = unpack2(acc[i][j]);
            float  e0 = expf((l.x - gm) * TEMP_INV);
            float  e1 = expf((l.y - gm) * TEMP_INV);
            float2 bb = __half22float2(b2[i][j]);
            float  h0 = sXT[(size_t)cj       * XTS + r];
            float  h1 = sXT[(size_t)(cj + 1) * XTS + r];
            s += e0 + e1;
            d = fmaf(e0 * h0 * bb.x, sWo[cj],     d);
            d = fmaf(e1 * h1 * bb.y, sWo[cj + 1], d);
        }
#pragma unroll
        for (int o = 16; o > 0; o >>= 1) {
            s += __shfl_xor_sync(FULL, s, o);
            d += __shfl_xor_sync(FULL, d, o);
        }
        if (tx == 0) { ps0[wid * 9 + i] = s; ps1[wid * 9 + i] = d; }
    }
    __syncthreads();

    // (3) finishers: combine halves, 1/sum, +alpha, write out
    if (tid < 32) {
        int r = tid, w1 = r >> 3, ri = r & 7;
        float gs  = ps0[w1 * 9 + ri] + ps0[(w1 + 4) * 9 + ri];
        float tot = ps1[w1 * 9 + ri] + ps1[(w1 + 4) * 9 + ri];
        float alpha = 0.f;
        const float4* sk4 = reinterpret_cast<const float4*>(sku + (size_t)(b0 + r) * SKUD);
#pragma unroll
        for (int q = 0; q < 16; q++) {
            float4 sv = sk4[q];
            alpha += sv.x * sWaWo[4 * q]     + sv.y * sWaWo[4 * q + 1]
                   + sv.z * sWaWo[4 * q + 2] + sv.w * sWaWo[4 * q + 3];
        }
        out[b0 + r] = tot / gs + alpha;
    }
}

extern "C" void kernel_launch(void* const* d_in, const int* in_sizes, int n_in,
                              void* d_out, int out_size)
{
    const float* inputs   = (const float*)d_in[0];
    const float* sku      = (const float*)d_in[1];
    const float* deltas   = (const float*)d_in[2];
    const float* ln_gamma = (const float*)d_in[3];
    const float* ln_beta  = (const float*)d_in[4];
    const float* attn_w   = (const float*)d_in[5];
    const float* Wh       = (const float*)d_in[6];
    const float* Wah      = (const float*)d_in[7];
    const float* Waa      = (const float*)d_in[8];
    const float* Wb       = (const float*)d_in[9];
    const float* Wa       = (const float*)d_in[10];
    const float* Wo       = (const float*)d_in[11];
    float* out = (float*)d_out;

    int B = in_sizes[0] / H;
    cudaFuncSetAttribute(holiday_fused_kernel,
                         cudaFuncAttributeMaxDynamicSharedMemorySize, SMEM_BYTES);
    holiday_fused_kernel<<<B / ROWS, NTHR, SMEM_BYTES>>>(
        inputs, sku, deltas, ln_gamma, ln_beta, attn_w,
        Wh, Wah, Waa, Wb, Wa, Wo, out);
}

// round 7
// speedup vs baseline: 1.6915x; 1.0018x over previous
#include <cuda_runtime.h>
#include <cuda_fp16.h>
#include <math.h>

namespace {
constexpr int H    = 16;
constexpr int C    = 32;
constexpr int HID  = 512;
constexpr int SKUD = 64;
constexpr int ROWS = 32;
constexpr int NTHR = 256;
constexpr int KT   = 8;
constexpr int XTS  = 36;     // X^T row stride (floats), 16B-aligned rows

constexpr float TEMP_INV = 1.0f / 0.7f;
constexpr float TMAX     = 365.0f;
constexpr float LN_EPS   = 1e-3f;

// shared layout (floats)
constexpr int OFF_XT   = 0;                    // 512*36 = 18432 (sku^T / X^T / H1^T)
constexpr int OFF_WT   = OFF_XT + 512 * XTS;   // 8*512 = 4096 (W k-tile)
constexpr int OFF_WO   = OFF_WT + KT * HID;    // 512
constexpr int OFF_PS0  = OFF_WO + HID;         // 8*9 = 72
constexpr int OFF_PS1  = OFF_PS0 + 72;         // 72
constexpr int OFF_GMAX = OFF_PS1 + 72;         // 32
constexpr int OFF_WAWO = OFF_GMAX + 32;        // 64
constexpr int SMEM_FLOATS = OFF_WAWO + SKUD;   // 23280
constexpr int SMEM_BYTES  = SMEM_FLOATS * 4;   // 93120 B -> 2 CTAs/SM
}

using ull = unsigned long long;

__device__ __forceinline__ ull pack2(float x, float y) {
    ull r; asm("mov.b64 %0, {%1, %2};" : "=l"(r) : "f"(x), "f"(y)); return r;
}
__device__ __forceinline__ float2 unpack2(ull v) {
    float2 f; asm("mov.b64 {%0, %1}, %2;" : "=f"(f.x), "=f"(f.y) : "l"(v)); return f;
}
__device__ __forceinline__ void ffma2(ull& d, ull a, ull b) {
    asm("fma.rn.f32x2 %0, %1, %2, %0;" : "+l"(d) : "l"(a), "l"(b));
}
__device__ __forceinline__ float mishf(float x) {
    float sp = (x > 20.f) ? x : log1pf(expf(x));
    return x * tanhf(sp);
}

// 8 rows x 8 cols per thread. acc[i][j] = f32x2 over cols (cj, cj+1) for row r0+i,
// cj = wcol + 64*j. W staged through shared in KT tiles (unrolled kk, immediate
// offsets). X^T rows broadcast via LDS.128. Contains __syncthreads: all call.
__device__ __forceinline__ void gemm8x8(
    const float* __restrict__ gW, int ktot,
    const float* __restrict__ sXT, int r0, int wcol,
    float* sWt, ull acc[8][4], int tid)
{
#pragma unroll
    for (int i = 0; i < 8; i++)
#pragma unroll
        for (int j = 0; j < 4; j++) acc[i][j] = 0ull;

    for (int kt = 0; kt < ktot; kt += KT) {
        __syncthreads();
        const float4* src = reinterpret_cast<const float4*>(gW + (size_t)kt * HID);
        float4*       dst = reinterpret_cast<float4*>(sWt);
#pragma unroll
        for (int i = 0; i < (KT * HID / 4) / NTHR; i++)
            dst[tid + i * NTHR] = src[tid + i * NTHR];
        __syncthreads();

        const float* xb = sXT + (size_t)kt * XTS + r0;
        const float* wb = sWt + wcol;
#pragma unroll
        for (int kk = 0; kk < KT; kk++) {
            float4 xa = *reinterpret_cast<const float4*>(xb + kk * XTS);      // rows r0..r0+3 (bcast)
            float4 xc = *reinterpret_cast<const float4*>(xb + kk * XTS + 4);  // rows r0+4..r0+7
            ull w2[4];
#pragma unroll
            for (int j = 0; j < 4; j++)
                w2[j] = *reinterpret_cast<const ull*>(wb + kk * HID + 64 * j);
            float xr[8] = {xa.x, xa.y, xa.z, xa.w, xc.x, xc.y, xc.z, xc.w};
#pragma unroll
            for (int i = 0; i < 8; i++) {
                ull xs = pack2(xr[i], xr[i]);
#pragma unroll
                for (int j = 0; j < 4; j++) ffma2(acc[i][j], xs, w2[j]);
            }
        }
    }
}

__global__ __launch_bounds__(NTHR, 2)
void holiday_fused_kernel(
    const float* __restrict__ inputs,     // [B,16]
    const float* __restrict__ sku,        // [B,64]
    const float* __restrict__ deltas,     // [16,32]
    const float* __restrict__ ln_gamma,   // [16,32]
    const float* __restrict__ ln_beta,    // [16,32]
    const float* __restrict__ attn_w,     // [16]
    const float* __restrict__ Wh,         // [16,32,32]
    const float* __restrict__ Wah,        // [512,512]
    const float* __restrict__ Waa,        // [512,512]
    const float* __restrict__ Wb,         // [64,512]
    const float* __restrict__ Wa,         // [64,512]
    const float* __restrict__ Wo,         // [512,1]
    float* __restrict__ out)              // [B]
{
    extern __shared__ float sm[];
    float* sXT   = sm + OFF_XT;
    float* sWt   = sm + OFF_WT;
    float* sWo   = sm + OFF_WO;
    float* ps0   = sm + OFF_PS0;
    float* ps1   = sm + OFF_PS1;
    float* gmaxA = sm + OFF_GMAX;
    float* sWaWo = sm + OFF_WAWO;

    const int tid  = threadIdx.x;
    const int tx   = tid & 31;
    const int wid  = tid >> 5;
    const int half = wid >> 2;          // col half (0/1): 256 cols each
    const int r0   = (wid & 3) * 8;     // this warp's 8 rows
    const int wcol = half * 256 + 2 * tx;
    const int b0   = blockIdx.x * ROWS;
    const unsigned FULL = 0xffffffffu;

    // ---- prologue: Wo -> smem; WaWo[s] = Wa[s,:].Wo (alpha fold) -----------
    for (int i = tid; i < HID; i += NTHR) sWo[i] = Wo[i];
#pragma unroll
    for (int si = 0; si < SKUD / 8; si++) {
        int s = wid * 8 + si;
        float p = 0.f;
#pragma unroll
        for (int j = 0; j < 16; j++) {
            int c = tx + 32 * j;
            p = fmaf(__ldg(Wa + s * HID + c), __ldg(Wo + c), p);
        }
#pragma unroll
        for (int o = 16; o > 0; o >>= 1) p += __shfl_xor_sync(FULL, p, o);
        if (tx == 0) sWaWo[s] = p;
    }

    // ---- changepoints via warp shuffle-scan --------------------------------
    float cps_r[2];
#pragma unroll
    for (int tt = 0; tt < 2; tt++) {
        int h = wid + 8 * tt;
        float d  = deltas[h * C + tx];
        float sp = (d > 20.f) ? d : log1pf(expf(d));
        float s  = sp;
#pragma unroll
        for (int o = 1; o < 32; o <<= 1) {
            float v = __shfl_up_sync(FULL, s, o);
            if (tx >= o) s += v;
        }
        float tot = __shfl_sync(FULL, s, 31);
        cps_r[tt] = s * (TMAX / tot);
    }

    // ---- stage sku^T into X^T rows 0..63 -----------------------------------
    {
        int r  = tid >> 3;
        int k0 = (tid & 7) * 8;
        const float4* s4 = reinterpret_cast<const float4*>(sku + (size_t)(b0 + r) * SKUD + k0);
        float4 a = s4[0], b = s4[1];
        sXT[(k0 + 0) * XTS + r] = a.x;  sXT[(k0 + 1) * XTS + r] = a.y;
        sXT[(k0 + 2) * XTS + r] = a.z;  sXT[(k0 + 3) * XTS + r] = a.w;
        sXT[(k0 + 4) * XTS + r] = b.x;  sXT[(k0 + 5) * XTS + r] = b.y;
        sXT[(k0 + 6) * XTS + r] = b.z;  sXT[(k0 + 7) * XTS + r] = b.w;
    }
    // (gemm8x8 opens with __syncthreads)

    ull acc[8][4];

    // ---- GEMM0: beta = sigmoid(sku @ Wb) -> registers (fp16x2) -------------
    gemm8x8(Wb, SKUD, sXT, r0, wcol, sWt, acc, tid);
    __half2 b2[8][4];
#pragma unroll
    for (int i = 0; i < 8; i++)
#pragma unroll
        for (int j = 0; j < 4; j++) {
            float2 v = unpack2(acc[i][j]);
            b2[i][j] = __floats2half2_rn(1.0f / (1.0f + expf(-v.x)),
                                         1.0f / (1.0f + expf(-v.y)));
        }
    __syncthreads();   // sku^T reads done -> stage1 may overwrite X^T

    // ---- stage 1: per-(row,holiday) features -> X^T ------------------------
#pragma unroll
    for (int tt = 0; tt < 2; tt++) {
        int h = wid + 8 * tt;          // warp-uniform
        float t = inputs[(size_t)(b0 + tx) * H + h];
        float f[C], e[C];
        float mu = 0.f;
#pragma unroll
        for (int c = 0; c < C; c++) {
            float cp = __shfl_sync(FULL, cps_r[tt], c);
            f[c] = fmaxf(t - cp, 0.f); mu += f[c];
        }
        mu *= (1.0f / C);
        float var = 0.f;
#pragma unroll
        for (int c = 0; c < C; c++) { float d = f[c] - mu; var = fmaf(d, d, var); }
        var *= (1.0f / C);
        float rs = rsqrtf(var + LN_EPS);
        float aw = __ldg(attn_w + h) * TEMP_INV;
        float m = -3.4e38f;
#pragma unroll
        for (int c = 0; c < C; c++) {
            float n = fmaf((f[c] - mu) * rs, __ldg(ln_gamma + h * C + c),
                           __ldg(ln_beta + h * C + c));
            f[c] = n;
            m = fmaxf(m, n * aw);
        }
        float s = 0.f;
#pragma unroll
        for (int c = 0; c < C; c++) { e[c] = expf(f[c] * aw - m); s += e[c]; }
        float inv = 1.0f / s;

        ull hid2[16];
#pragma unroll
        for (int d = 0; d < 16; d++) hid2[d] = 0ull;
#pragma unroll
        for (int c = 0; c < C; c++) {
            float a = f[c] * e[c] * inv;
            ull a2 = pack2(a, a);
            const ull* wr = reinterpret_cast<const ull*>(Wh + (h * C + c) * C);
#pragma unroll
            for (int d = 0; d < 16; d++) ffma2(hid2[d], a2, wr[d]);
        }
#pragma unroll
        for (int d = 0; d < 16; d++) {
            float2 hv = unpack2(hid2[d]);
            sXT[(h * 32 + 2 * d)     * XTS + tx] = mishf(hv.x);
            sXT[(h * 32 + 2 * d + 1) * XTS + tx] = mishf(hv.y);
        }
    }
    // (gemm8x8 opens with __syncthreads -> X^T visible)

    // ---- GEMM1: H1 = mish(X @ Wah) -----------------------------------------
    gemm8x8(Wah, HID, sXT, r0, wcol, sWt, acc, tid);
    __syncthreads();   // all X^T reads done; overwrite with H1^T
#pragma unroll
    for (int i = 0; i < 8; i++)
#pragma unroll
        for (int j = 0; j < 4; j++) {
            float2 v = unpack2(acc[i][j]);
            int cj = wcol + 64 * j;
            sXT[(size_t)cj       * XTS + r0 + i] = mishf(v.x);
            sXT[(size_t)(cj + 1) * XTS + r0 + i] = mishf(v.y);
        }
    // (gemm8x8 opens with __syncthreads -> H1^T visible)

    // ---- GEMM2: logits = H1 @ Waa (stays in registers) ---------------------
    gemm8x8(Waa, HID, sXT, r0, wcol, sWt, acc, tid);

    // ---- epilogue ----------------------------------------------------------
    // (1) row max
#pragma unroll
    for (int i = 0; i < 8; i++) {
        float m = -3.4e38f;
#pragma unroll
        for (int j = 0; j < 4; j++) {
            float2 l = unpack2(acc[i][j]);
            m = fmaxf(m, fmaxf(l.x, l.y));
        }
#pragma unroll
        for (int o = 16; o > 0; o >>= 1) m = fmaxf(m, __shfl_xor_sync(FULL, m, o));
        if (tx == 0) ps0[wid * 9 + i] = m;
    }
    __syncthreads();
    if (tid < 32) {
        int r = tid, w1 = r >> 3;
        gmaxA[r] = fmaxf(ps0[w1 * 9 + (r & 7)], ps0[(w1 + 4) * 9 + (r & 7)]);
    }
    __syncthreads();

    // (2) exp-sum + weighted dot (e * H1 * beta * Wo), per row
#pragma unroll
    for (int i = 0; i < 8; i++) {
        int r = r0 + i;
        float gm = gmaxA[r];
        float s = 0.f, d = 0.f;
#pragma unroll
        for (int j = 0; j < 4; j++) {
            int cj = wcol + 64 * j;
            float2 l  = unpack2(acc[i][j]);
            float  e0 = expf((l.x - gm) * TEMP_INV);
            float  e1 = expf((l.y - gm) * TEMP_INV);
            float2 bb = __half22float2(b2[i][j]);
            float  h0 = sXT[(size_t)cj       * XTS + r];
            float  h1 = sXT[(size_t)(cj + 1) * XTS + r];
            s += e0 + e1;
            d = fmaf(e0 * h0 * bb.x, sWo[cj],     d);
            d = fmaf(e1 * h1 * bb.y, sWo[cj + 1], d);
        }
#pragma unroll
        for (int o = 16; o > 0; o >>= 1) {
            s += __shfl_xor_sync(FULL, s, o);
            d += __shfl_xor_sync(FULL, d, o);
        }
        if (tx == 0) { ps0[wid * 9 + i] = s; ps1[wid * 9 + i] = d; }
    }
    __syncthreads();

    // (3) finishers: combine halves, 1/sum, +alpha, write out
    if (tid < 32) {
        int r = tid, w1 = r >> 3, ri = r & 7;
        float gs  = ps0[w1 * 9 + ri] + ps0[(w1 + 4) * 9 + ri];
        float tot = ps1[w1 * 9 + ri] + ps1[(w1 + 4) * 9 + ri];
        float alpha = 0.f;
        const float4* sk4 = reinterpret_cast<const float4*>(sku + (size_t)(b0 + r) * SKUD);
#pragma unroll
        for (int q = 0; q < 16; q++) {
            float4 sv = sk4[q];
            alpha += sv.x * sWaWo[4 * q]     + sv.y * sWaWo[4 * q + 1]
                   + sv.z * sWaWo[4 * q + 2] + sv.w * sWaWo[4 * q + 3];
        }
        out[b0 + r] = tot / gs + alpha;
    }
}

extern "C" void kernel_launch(void* const* d_in, const int* in_sizes, int n_in,
                              void* d_out, int out_size)
{
    const float* inputs   = (const float*)d_in[0];
    const float* sku      = (const float*)d_in[1];
    const float* deltas   = (const float*)d_in[2];
    const float* ln_gamma = (const float*)d_in[3];
    const float* ln_beta  = (const float*)d_in[4];
    const float* attn_w   = (const float*)d_in[5];
    const float* Wh       = (const float*)d_in[6];
    const float* Wah      = (const float*)d_in[7];
    const float* Waa      = (const float*)d_in[8];
    const float* Wb       = (const float*)d_in[9];
    const float* Wa       = (const float*)d_in[10];
    const float* Wo       = (const float*)d_in[11];
    float* out = (float*)d_out;

    int B = in_sizes[0] / H;
    cudaFuncSetAttribute(holiday_fused_kernel,
                         cudaFuncAttributeMaxDynamicSharedMemorySize, SMEM_BYTES);
    holiday_fused_kernel<<<B / ROWS, NTHR, SMEM_BYTES>>>(
        inputs, sku, deltas, ln_gamma, ln_beta, attn_w,
        Wh, Wah, Waa, Wb, Wa, Wo, out);
}

// round 9
// speedup vs baseline: 1.8122x; 1.0714x over previous
#include <cuda_runtime.h>
#include <cuda_fp16.h>
#include <math.h>
#include <stdint.h>

namespace {
constexpr int H    = 16;
constexpr int C    = 32;
constexpr int HID  = 512;
constexpr int SKUD = 64;
constexpr int ROWS = 32;
constexpr int NTHR = 256;
constexpr int KT   = 8;
constexpr int XTS  = 36;     // X^T row stride (floats), 16B-aligned rows

constexpr float TEMP_INV = 1.0f / 0.7f;
constexpr float TMAX     = 365.0f;
constexpr float LN_EPS   = 1e-3f;

// shared layout (floats)
constexpr int OFF_XT   = 0;                    // 512*36 = 18432 (sku^T / X^T / H1^T)
constexpr int OFF_W0   = OFF_XT + 512 * XTS;   // 4096 (W tile, buffer 0)
constexpr int OFF_W1   = OFF_W0 + KT * HID;    // 4096 (W tile, buffer 1)
constexpr int OFF_WO   = OFF_W1 + KT * HID;    // 512
constexpr int OFF_PS0  = OFF_WO + HID;         // 8*9 = 72
constexpr int OFF_PS1  = OFF_PS0 + 72;         // 72
constexpr int OFF_GMAX = OFF_PS1 + 72;         // 32
constexpr int OFF_WAWO = OFF_GMAX + 32;        // 64
constexpr int SMEM_FLOATS = OFF_WAWO + SKUD;   // 27376
constexpr int SMEM_BYTES  = SMEM_FLOATS * 4;   // 109504 B -> 2 CTAs/SM
}

using ull = unsigned long long;

__device__ __forceinline__ ull pack2(float x, float y) {
    ull r; asm("mov.b64 %0, {%1, %2};" : "=l"(r) : "f"(x), "f"(y)); return r;
}
__device__ __forceinline__ float2 unpack2(ull v) {
    float2 f; asm("mov.b64 {%0, %1}, %2;" : "=f"(f.x), "=f"(f.y) : "l"(v)); return f;
}
__device__ __forceinline__ void ffma2(ull& d, ull a, ull b) {
    asm("fma.rn.f32x2 %0, %1, %2, %0;" : "+l"(d) : "l"(a), "l"(b));
}
__device__ __forceinline__ float mishf(float x) {
    float sp = (x > 20.f) ? x : log1pf(expf(x));
    return x * tanhf(sp);
}
__device__ __forceinline__ uint32_t s2u(const void* p) {
    uint32_t a;
    asm("{ .reg .u64 t; cvta.to.shared.u64 t, %1; cvt.u32.u64 %0, t; }" : "=r"(a) : "l"(p));
    return a;
}
// async-copy one KT x HID tile (16KB): 4 x 16B per thread, then commit.
__device__ __forceinline__ void cp_tile(float* dst, const float* __restrict__ src, int tid) {
    uint32_t d = s2u(dst) + tid * 16;
    const float* s = src + tid * 4;
#pragma unroll
    for (int i = 0; i < 4; i++)
        asm volatile("cp.async.cg.shared.global [%0], [%1], 16;"
                     :: "r"(d + i * NTHR * 16), "l"(s + i * NTHR * 4) : "memory");
    asm volatile("cp.async.commit_group;" ::: "memory");
}
__device__ __forceinline__ void cp_wait_all() {
    asm volatile("cp.async.wait_group 0;" ::: "memory");
}

// 8 rows x 8 cols per thread; double-buffered cp.async W streaming.
// acc[i][j] = f32x2 over cols (cj, cj+1), cj = wcol + 64*j, row r0+i.
// One __syncthreads per tile; prefetch of tile t+1 overlaps compute of tile t.
// Contains __syncthreads: all threads must call.
__device__ __forceinline__ void gemm8x8(
    const float* __restrict__ gW, int ktot,
    const float* __restrict__ sXT, int r0, int wcol,
    float* sW0, float* sW1, ull acc[8][4], int tid)
{
#pragma unroll
    for (int i = 0; i < 8; i++)
#pragma unroll
        for (int j = 0; j < 4; j++) acc[i][j] = 0ull;

    const int nt = ktot / KT;          // 8 or 64 (always even)
    cp_tile(sW0, gW, tid);
    for (int t = 0; t < nt; t++) {
        float* cur = (t & 1) ? sW1 : sW0;
        float* nxt = (t & 1) ? sW0 : sW1;
        cp_wait_all();                 // current tile landed (this thread's part)
        __syncthreads();               // all parts landed; prev tile fully consumed
        if (t + 1 < nt) cp_tile(nxt, gW + (size_t)(t + 1) * KT * HID, tid);

        const float* xb = sXT + (size_t)t * KT * XTS + r0;
        const float* wb = cur + wcol;
#pragma unroll
        for (int kk = 0; kk < KT; kk++) {
            float4 xa = *reinterpret_cast<const float4*>(xb + kk * XTS);      // rows r0..r0+3 (bcast)
            float4 xc = *reinterpret_cast<const float4*>(xb + kk * XTS + 4);  // rows r0+4..r0+7
            ull w2[4];
#pragma unroll
            for (int j = 0; j < 4; j++)
                w2[j] = *reinterpret_cast<const ull*>(wb + kk * HID + 64 * j);
            float xr[8] = {xa.x, xa.y, xa.z, xa.w, xc.x, xc.y, xc.z, xc.w};
#pragma unroll
            for (int i = 0; i < 8; i++) {
                ull xs = pack2(xr[i], xr[i]);
#pragma unroll
                for (int j = 0; j < 4; j++) ffma2(acc[i][j], xs, w2[j]);
            }
        }
    }
}

__global__ __launch_bounds__(NTHR, 2)
void holiday_fused_kernel(
    const float* __restrict__ inputs,     // [B,16]
    const float* __restrict__ sku,        // [B,64]
    const float* __restrict__ deltas,     // [16,32]
    const float* __restrict__ ln_gamma,   // [16,32]
    const float* __restrict__ ln_beta,    // [16,32]
    const float* __restrict__ attn_w,     // [16]
    const float* __restrict__ Wh,         // [16,32,32]
    const float* __restrict__ Wah,        // [512,512]
    const float* __restrict__ Waa,        // [512,512]
    const float* __restrict__ Wb,         // [64,512]
    const float* __restrict__ Wa,         // [64,512]
    const float* __restrict__ Wo,         // [512,1]
    float* __restrict__ out)              // [B]
{
    extern __shared__ float sm[];
    float* sXT   = sm + OFF_XT;
    float* sW0   = sm + OFF_W0;
    float* sW1   = sm + OFF_W1;
    float* sWo   = sm + OFF_WO;
    float* ps0   = sm + OFF_PS0;
    float* ps1   = sm + OFF_PS1;
    float* gmaxA = sm + OFF_GMAX;
    float* sWaWo = sm + OFF_WAWO;

    const int tid  = threadIdx.x;
    const int tx   = tid & 31;
    const int wid  = tid >> 5;
    const int half = wid >> 2;          // col half (0/1): 256 cols each
    const int r0   = (wid & 3) * 8;     // this warp's 8 rows
    const int wcol = half * 256 + 2 * tx;
    const int b0   = blockIdx.x * ROWS;
    const unsigned FULL = 0xffffffffu;

    // ---- prologue: Wo -> smem; WaWo[s] = Wa[s,:].Wo (alpha fold) -----------
    for (int i = tid; i < HID; i += NTHR) sWo[i] = Wo[i];
#pragma unroll
    for (int si = 0; si < SKUD / 8; si++) {
        int s = wid * 8 + si;
        float p = 0.f;
#pragma unroll
        for (int j = 0; j < 16; j++) {
            int c = tx + 32 * j;
            p = fmaf(__ldg(Wa + s * HID + c), __ldg(Wo + c), p);
        }
#pragma unroll
        for (int o = 16; o > 0; o >>= 1) p += __shfl_xor_sync(FULL, p, o);
        if (tx == 0) sWaWo[s] = p;
    }

    // ---- changepoints via warp shuffle-scan --------------------------------
    float cps_r[2];
#pragma unroll
    for (int tt = 0; tt < 2; tt++) {
        int h = wid + 8 * tt;
        float d  = deltas[h * C + tx];
        float sp = (d > 20.f) ? d : log1pf(expf(d));
        float s  = sp;
#pragma unroll
        for (int o = 1; o < 32; o <<= 1) {
            float v = __shfl_up_sync(FULL, s, o);
            if (tx >= o) s += v;
        }
        float tot = __shfl_sync(FULL, s, 31);
        cps_r[tt] = s * (TMAX / tot);
    }

    // ---- stage sku^T into X^T rows 0..63 -----------------------------------
    {
        int r  = tid >> 3;
        int k0 = (tid & 7) * 8;
        const float4* s4 = reinterpret_cast<const float4*>(sku + (size_t)(b0 + r) * SKUD + k0);
        float4 a = s4[0], b = s4[1];
        sXT[(k0 + 0) * XTS + r] = a.x;  sXT[(k0 + 1) * XTS + r] = a.y;
        sXT[(k0 + 2) * XTS + r] = a.z;  sXT[(k0 + 3) * XTS + r] = a.w;
        sXT[(k0 + 4) * XTS + r] = b.x;  sXT[(k0 + 5) * XTS + r] = b.y;
        sXT[(k0 + 6) * XTS + r] = b.z;  sXT[(k0 + 7) * XTS + r] = b.w;
    }
    // (gemm8x8's first in-loop __syncthreads makes sku^T visible)

    ull acc[8][4];

    // ---- GEMM0: beta = sigmoid(sku @ Wb) -> registers (fp16x2) -------------
    gemm8x8(Wb, SKUD, sXT, r0, wcol, sW0, sW1, acc, tid);
    __half2 b2[8][4];
#pragma unroll
    for (int i = 0; i < 8; i++)
#pragma unroll
        for (int j = 0; j < 4; j++) {
            float2 v = unpack2(acc[i][j]);
            b2[i][j] = __floats2half2_rn(1.0f / (1.0f + expf(-v.x)),
                                         1.0f / (1.0f + expf(-v.y)));
        }
    __syncthreads();   // sku^T reads done -> stage1 may overwrite X^T

    // ---- stage 1: per-(row,holiday) features -> X^T ------------------------
#pragma unroll
    for (int tt = 0; tt < 2; tt++) {
        int h = wid + 8 * tt;          // warp-uniform
        float t = inputs[(size_t)(b0 + tx) * H + h];
        float f[C], e[C];
        float mu = 0.f;
#pragma unroll
        for (int c = 0; c < C; c++) {
            float cp = __shfl_sync(FULL, cps_r[tt], c);
            f[c] = fmaxf(t - cp, 0.f); mu += f[c];
        }
        mu *= (1.0f / C);
        float var = 0.f;
#pragma unroll
        for (int c = 0; c < C; c++) { float d = f[c] - mu; var = fmaf(d, d, var); }
        var *= (1.0f / C);
        float rs = rsqrtf(var + LN_EPS);
        float aw = __ldg(attn_w + h) * TEMP_INV;
        float m = -3.4e38f;
#pragma unroll
        for (int c = 0; c < C; c++) {
            float n = fmaf((f[c] - mu) * rs, __ldg(ln_gamma + h * C + c),
                           __ldg(ln_beta + h * C + c));
            f[c] = n;
            m = fmaxf(m, n * aw);
        }
        float s = 0.f;
#pragma unroll
        for (int c = 0; c < C; c++) { e[c] = expf(f[c] * aw - m); s += e[c]; }
        float inv = 1.0f / s;

        ull hid2[16];
#pragma unroll
        for (int d = 0; d < 16; d++) hid2[d] = 0ull;
#pragma unroll
        for (int c = 0; c < C; c++) {
            float a = f[c] * e[c] * inv;
            ull a2 = pack2(a, a);
            const ull* wr = reinterpret_cast<const ull*>(Wh + (h * C + c) * C);
#pragma unroll
            for (int d = 0; d < 16; d++) ffma2(hid2[d], a2, wr[d]);
        }
#pragma unroll
        for (int d = 0; d < 16; d++) {
            float2 hv = unpack2(hid2[d]);
            sXT[(h * 32 + 2 * d)     * XTS + tx] = mishf(hv.x);
            sXT[(h * 32 + 2 * d + 1) * XTS + tx] = mishf(hv.y);
        }
    }
    __syncthreads();   // X^T ready before GEMM1 reads it

    // ---- GEMM1: H1 = mish(X @ Wah) -----------------------------------------
    gemm8x8(Wah, HID, sXT, r0, wcol, sW0, sW1, acc, tid);
    __syncthreads();   // all X^T reads done; overwrite with H1^T
#pragma unroll
    for (int i = 0; i < 8; i++)
#pragma unroll
        for (int j = 0; j < 4; j++) {
            float2 v = unpack2(acc[i][j]);
            int cj = wcol + 64 * j;
            sXT[(size_t)cj       * XTS + r0 + i] = mishf(v.x);
            sXT[(size_t)(cj + 1) * XTS + r0 + i] = mishf(v.y);
        }
    __syncthreads();   // H1^T ready

    // ---- GEMM2: logits = H1 @ Waa (stays in registers) ---------------------
    gemm8x8(Waa, HID, sXT, r0, wcol, sW0, sW1, acc, tid);

    // ---- epilogue ----------------------------------------------------------
    // (1) row max
#pragma unroll
    for (int i = 0; i < 8; i++) {
        float m = -3.4e38f;
#pragma unroll
        for (int j = 0; j < 4; j++) {
            float2 l = unpack2(acc[i][j]);
            m = fmaxf(m, fmaxf(l.x, l.y));
        }
#pragma unroll
        for (int o = 16; o > 0; o >>= 1) m = fmaxf(m, __shfl_xor_sync(FULL, m, o));
        if (tx == 0) ps0[wid * 9 + i] = m;
    }
    __syncthreads();
    if (tid < 32) {
        int r = tid, w1 = r >> 3;
        gmaxA[r] = fmaxf(ps0[w1 * 9 + (r & 7)], ps0[(w1 + 4) * 9 + (r & 7)]);
    }
    __syncthreads();

    // (2) exp-sum + weighted dot (e * H1 * beta * Wo), per row
#pragma unroll
    for (int i = 0; i < 8; i++) {
        int r = r0 + i;
        float gm = gmaxA[r];
        float s = 0.f, d = 0.f;
#pragma unroll
        for (int j = 0; j < 4; j++) {
            int cj = wcol + 64 * j;
            float2 l  = unpack2(acc[i][j]);
            float  e0 = expf((l.x - gm) * TEMP_INV);
            float  e1 = expf((l.y - gm) * TEMP_INV);
            float2 bb = __half22float2(b2[i][j]);
            float  h0 = sXT[(size_t)cj       * XTS + r];
            float  h1 = sXT[(size_t)(cj + 1) * XTS + r];
            s += e0 + e1;
            d = fmaf(e0 * h0 * bb.x, sWo[cj],     d);
            d = fmaf(e1 * h1 * bb.y, sWo[cj + 1], d);
        }
#pragma unroll
        for (int o = 16; o > 0; o >>= 1) {
            s += __shfl_xor_sync(FULL, s, o);
            d += __shfl_xor_sync(FULL, d, o);
        }
        if (tx == 0) { ps0[wid * 9 + i] = s; ps1[wid * 9 + i] = d; }
    }
    __syncthreads();

    // (3) finishers: combine halves, 1/sum, +alpha, write out
    if (tid < 32) {
        int r = tid, w1 = r >> 3, ri = r & 7;
        float gs  = ps0[w1 * 9 + ri] + ps0[(w1 + 4) * 9 + ri];
        float tot = ps1[w1 * 9 + ri] + ps1[(w1 + 4) * 9 + ri];
        float alpha = 0.f;
        const float4* sk4 = reinterpret_cast<const float4*>(sku + (size_t)(b0 + r) * SKUD);
#pragma unroll
        for (int q = 0; q < 16; q++) {
            float4 sv = sk4[q];
            alpha += sv.x * sWaWo[4 * q]     + sv.y * sWaWo[4 * q + 1]
                   + sv.z * sWaWo[4 * q + 2] + sv.w * sWaWo[4 * q + 3];
        }
        out[b0 + r] = tot / gs + alpha;
    }
}

extern "C" void kernel_launch(void* const* d_in, const int* in_sizes, int n_in,
                              void* d_out, int out_size)
{
    const float* inputs   = (const float*)d_in[0];
    const float* sku      = (const float*)d_in[1];
    const float* deltas   = (const float*)d_in[2];
    const float* ln_gamma = (const float*)d_in[3];
    const float* ln_beta  = (const float*)d_in[4];
    const float* attn_w   = (const float*)d_in[5];
    const float* Wh       = (const float*)d_in[6];
    const float* Wah      = (const float*)d_in[7];
    const float* Waa      = (const float*)d_in[8];
    const float* Wb       = (const float*)d_in[9];
    const float* Wa       = (const float*)d_in[10];
    const float* Wo       = (const float*)d_in[11];
    float* out = (float*)d_out;

    int B = in_sizes[0] / H;
    cudaFuncSetAttribute(holiday_fused_kernel,
                         cudaFuncAttributeMaxDynamicSharedMemorySize, SMEM_BYTES);
    holiday_fused_kernel<<<B / ROWS, NTHR, SMEM_BYTES>>>(
        inputs, sku, deltas, ln_gamma, ln_beta, attn_w,
        Wh, Wah, Waa, Wb, Wa, Wo, out);
}

// round 10
// speedup vs baseline: 2.1880x; 1.2074x over previous
#include <cuda_runtime.h>
#include <cuda_fp16.h>
#include <cuda_bf16.h>
#include <math.h>
#include <stdint.h>

// prep-built weight images in B-fragment order: idx = ((kb*64+nb)*32+lane)*2+reg
__device__ __align__(16) uint32_t gWahHi[131072];
__device__ __align__(16) uint32_t gWahLo[131072];
__device__ __align__(16) uint32_t gWaaHi[131072];
__device__ __align__(16) uint32_t gWaaLo[131072];
__device__ __align__(16) uint32_t gWbHi [16384];
__device__ __align__(16) uint32_t gWbLo [16384];

namespace {
constexpr int H = 16, C = 32, HID = 512, SKUD = 64, ROWS = 32, NTHR = 256;
constexpr float TEMP_INV = 1.0f / 0.7f, TMAX = 365.0f, LN_EPS = 1e-3f;
constexpr int XSTR = 1040;                 // X image row stride (520 bf16)
// smem byte offsets
constexpr int OFF_XHI = 0;                 // 32*1040 = 33280
constexpr int OFF_XLO = 33280;
constexpr int OFF_WC  = 66560;             // W chunk ring: 2 x (16KB hi + 16KB lo)
constexpr int OFF_WO  = 132096;            // 512 f32
constexpr int OFF_PS0 = 134144;            // 8*32 f32
constexpr int OFF_PS1 = 135168;
constexpr int OFF_GMX = 136192;            // 32 f32
constexpr int OFF_WAWO= 136320;            // 64 f32
constexpr int SMEM_BYTES = 136576;
}

using ull = unsigned long long;

__device__ __forceinline__ ull pack2(float x, float y) {
    ull r; asm("mov.b64 %0, {%1, %2};" : "=l"(r) : "f"(x), "f"(y)); return r;
}
__device__ __forceinline__ float2 unpack2(ull v) {
    float2 f; asm("mov.b64 {%0, %1}, %2;" : "=f"(f.x), "=f"(f.y) : "l"(v)); return f;
}
__device__ __forceinline__ void ffma2(ull& d, ull a, ull b) {
    asm("fma.rn.f32x2 %0, %1, %2, %0;" : "+l"(d) : "l"(a), "l"(b));
}
__device__ __forceinline__ float mishf(float x) {
    float sp = (x > 20.f) ? x : log1pf(expf(x));
    return x * tanhf(sp);
}
__device__ __forceinline__ uint32_t s2u(const void* p) {
    uint32_t a;
    asm("{ .reg .u64 t; cvta.to.shared.u64 t, %1; cvt.u32.u64 %0, t; }" : "=r"(a) : "l"(p));
    return a;
}
__device__ __forceinline__ uint32_t packbf2(float a, float b) {
    __nv_bfloat162 v = __floats2bfloat162_rn(a, b);   // lo=a, hi=b
    return *reinterpret_cast<uint32_t*>(&v);
}
__device__ __forceinline__ float2 unbf2(uint32_t u) {
    __nv_bfloat162 v = *reinterpret_cast<__nv_bfloat162*>(&u);
    return make_float2(__bfloat162float(v.x), __bfloat162float(v.y));
}
__device__ __forceinline__ void hmma(float* acc, uint32_t a0, uint32_t a1,
                                     uint32_t a2, uint32_t a3, uint32_t b0, uint32_t b1) {
    asm volatile("mma.sync.aligned.m16n8k16.row.col.f32.bf16.bf16.f32 "
        "{%0,%1,%2,%3}, {%4,%5,%6,%7}, {%8,%9}, {%0,%1,%2,%3};"
        : "+f"(acc[0]), "+f"(acc[1]), "+f"(acc[2]), "+f"(acc[3])
        : "r"(a0), "r"(a1), "r"(a2), "r"(a3), "r"(b0), "r"(b1));
}

// cp.async one W chunk (hi 16KB + lo 16KB) into ring slot s
__device__ __forceinline__ void cp_chunk(char* smc, int s,
                                         const uint32_t* gHi, const uint32_t* gLo,
                                         int kb, int tid) {
    uint32_t dH = s2u(smc + OFF_WC + s * 32768) + tid * 16;
    uint32_t dL = dH + 16384;
    const char* sH = (const char*)(gHi + kb * 4096) + tid * 16;
    const char* sL = (const char*)(gLo + kb * 4096) + tid * 16;
#pragma unroll
    for (int i = 0; i < 4; i++) {
        asm volatile("cp.async.cg.shared.global [%0], [%1], 16;"
                     :: "r"(dH + i * 4096), "l"(sH + i * 4096) : "memory");
        asm volatile("cp.async.cg.shared.global [%0], [%1], 16;"
                     :: "r"(dL + i * 4096), "l"(sL + i * 4096) : "memory");
    }
    asm volatile("cp.async.commit_group;" ::: "memory");
}
__device__ __forceinline__ void cp_wait_all() {
    asm volatile("cp.async.wait_group 0;" ::: "memory");
}

// split-bf16 MMA GEMM: acc[mi][nb][4] over warp-tile 32 rows x 64 cols.
// A = X images (hi/lo) in smem; B = prep-built frag-order W images streamed
// via cp.async double buffer. Contains __syncthreads: all threads call.
__device__ void mma_gemm(const uint32_t* gHi, const uint32_t* gLo, int nk,
                         char* smc, float acc[2][8][4], int tid, int wid, int tx)
{
#pragma unroll
    for (int mi = 0; mi < 2; mi++)
#pragma unroll
        for (int nb = 0; nb < 8; nb++)
#pragma unroll
            for (int e = 0; e < 4; e++) acc[mi][nb][e] = 0.f;

    const int tg = tx & 3, gq = tx >> 2;
    const int wn0 = wid * 64;

    cp_chunk(smc, 0, gHi, gLo, 0, tid);
    for (int kb = 0; kb < nk; kb++) {
        int s = kb & 1;
        cp_wait_all();
        __syncthreads();
        if (kb + 1 < nk) cp_chunk(smc, s ^ 1, gHi, gLo, kb + 1, tid);

        // A fragments: 4 x u32 per (mi, img)
        uint32_t ah[2][4], al[2][4];
#pragma unroll
        for (int mi = 0; mi < 2; mi++) {
            int base = (mi * 16 + gq) * XSTR + kb * 32 + 4 * tg;
            ah[mi][0] = *(const uint32_t*)(smc + OFF_XHI + base);
            ah[mi][1] = *(const uint32_t*)(smc + OFF_XHI + base + 8 * XSTR);
            ah[mi][2] = *(const uint32_t*)(smc + OFF_XHI + base + 16);
            ah[mi][3] = *(const uint32_t*)(smc + OFF_XHI + base + 8 * XSTR + 16);
            al[mi][0] = *(const uint32_t*)(smc + OFF_XLO + base);
            al[mi][1] = *(const uint32_t*)(smc + OFF_XLO + base + 8 * XSTR);
            al[mi][2] = *(const uint32_t*)(smc + OFF_XLO + base + 16);
            al[mi][3] = *(const uint32_t*)(smc + OFF_XLO + base + 8 * XSTR + 16);
        }
        const char* cb = smc + OFF_WC + s * 32768;
#pragma unroll
        for (int nb = 0; nb < 8; nb++) {
            int nbg = (wn0 >> 3) + nb;
            ull bh2 = *(const ull*)(cb + (nbg * 32 + tx) * 8);
            ull bl2 = *(const ull*)(cb + 16384 + (nbg * 32 + tx) * 8);
            uint32_t bh0 = (uint32_t)bh2, bh1 = (uint32_t)(bh2 >> 32);
            uint32_t bl0 = (uint32_t)bl2, bl1 = (uint32_t)(bl2 >> 32);
#pragma unroll
            for (int mi = 0; mi < 2; mi++) {
                hmma(acc[mi][nb], ah[mi][0], ah[mi][1], ah[mi][2], ah[mi][3], bh0, bh1);
                hmma(acc[mi][nb], ah[mi][0], ah[mi][1], ah[mi][2], ah[mi][3], bl0, bl1);
                hmma(acc[mi][nb], al[mi][0], al[mi][1], al[mi][2], al[mi][3], bh0, bh1);
            }
        }
    }
}

// ---------- prep: build frag-order bf16 hi/lo weight images ------------------
__global__ void prep_kernel(const float* __restrict__ Wah,
                            const float* __restrict__ Waa,
                            const float* __restrict__ Wb)
{
    int gid = blockIdx.x * 256 + threadIdx.x;
    const float* W; uint32_t *dHi, *dLo; int idx;
    if (gid < 131072)      { W = Wah; dHi = gWahHi; dLo = gWahLo; idx = gid; }
    else if (gid < 262144) { W = Waa; dHi = gWaaHi; dLo = gWaaLo; idx = gid - 131072; }
    else                   { W = Wb;  dHi = gWbHi;  dLo = gWbLo;  idx = gid - 262144; }
    int reg = idx & 1, lane = (idx >> 1) & 31, nb = (idx >> 6) & 63, kb = idx >> 12;
    int tg = lane & 3, gq = lane >> 2;
    int k0 = kb * 16 + 2 * tg + reg * 8;
    int n  = nb * 8 + gq;
    float w0 = W[(size_t)k0 * 512 + n];
    float w1 = W[(size_t)(k0 + 1) * 512 + n];
    __nv_bfloat16 h0 = __float2bfloat16(w0), h1 = __float2bfloat16(w1);
    float l0f = w0 - __bfloat162float(h0), l1f = w1 - __bfloat162float(h1);
    __nv_bfloat162 hv(h0, h1);
    __nv_bfloat162 lv(__float2bfloat16(l0f), __float2bfloat16(l1f));
    dHi[idx] = *reinterpret_cast<uint32_t*>(&hv);
    dLo[idx] = *reinterpret_cast<uint32_t*>(&lv);
}

__global__ __launch_bounds__(NTHR)
void holiday_mma_kernel(
    const float* __restrict__ inputs, const float* __restrict__ sku,
    const float* __restrict__ deltas, const float* __restrict__ ln_gamma,
    const float* __restrict__ ln_beta, const float* __restrict__ attn_w,
    const float* __restrict__ Wh, const float* __restrict__ Wa,
    const float* __restrict__ Wo, float* __restrict__ out)
{
    extern __shared__ char smc[];
    float* sWo   = (float*)(smc + OFF_WO);
    float* ps0   = (float*)(smc + OFF_PS0);
    float* ps1   = (float*)(smc + OFF_PS1);
    float* gmaxA = (float*)(smc + OFF_GMX);
    float* sWaWo = (float*)(smc + OFF_WAWO);

    const int tid = threadIdx.x, tx = tid & 31, wid = tid >> 5;
    const int tg = tx & 3, gq = tx >> 2;
    const int wn0 = wid * 64;
    const int b0 = blockIdx.x * ROWS;
    const unsigned FULL = 0xffffffffu;

    // ---- prologue: Wo, alpha fold, changepoints ----------------------------
    for (int i = tid; i < HID; i += NTHR) sWo[i] = Wo[i];
#pragma unroll
    for (int si = 0; si < SKUD / 8; si++) {
        int s = wid * 8 + si;
        float p = 0.f;
#pragma unroll
        for (int j = 0; j < 16; j++) {
            int c = tx + 32 * j;
            p = fmaf(__ldg(Wa + s * HID + c), __ldg(Wo + c), p);
        }
#pragma unroll
        for (int o = 16; o > 0; o >>= 1) p += __shfl_xor_sync(FULL, p, o);
        if (tx == 0) sWaWo[s] = p;
    }
    float cps_r[2];
#pragma unroll
    for (int tt = 0; tt < 2; tt++) {
        int h = wid + 8 * tt;
        float d  = deltas[h * C + tx];
        float sp = (d > 20.f) ? d : log1pf(expf(d));
        float s  = sp;
#pragma unroll
        for (int o = 1; o < 32; o <<= 1) {
            float v = __shfl_up_sync(FULL, s, o);
            if (tx >= o) s += v;
        }
        cps_r[tt] = s * (TMAX / __shfl_sync(FULL, s, 31));
    }

    // ---- stage sku into X images (rows 0..31, k 0..63) ---------------------
    {
        int r = tid >> 3, k0 = (tid & 7) * 8;
        const float4* s4 = (const float4*)(sku + (size_t)(b0 + r) * SKUD + k0);
        float4 a = s4[0], b = s4[1];
        float v[8] = {a.x, a.y, a.z, a.w, b.x, b.y, b.z, b.w};
#pragma unroll
        for (int e = 0; e < 4; e++) {
            float v0 = v[2 * e], v1 = v[2 * e + 1];
            __nv_bfloat16 h0 = __float2bfloat16(v0), h1 = __float2bfloat16(v1);
            uint32_t off = r * XSTR + (k0 + 2 * e) * 2;
            *(uint32_t*)(smc + OFF_XHI + off) = packbf2(v0, v1);  // rn of full value
            // hi must be truncation-consistent with lo:
            *(uint32_t*)(smc + OFF_XHI + off) =
                *(uint32_t*)&(*(__nv_bfloat162*)&(__nv_bfloat162(h0, h1)));
            float l0 = v0 - __bfloat162float(h0), l1 = v1 - __bfloat162float(h1);
            *(uint32_t*)(smc + OFF_XLO + off) = packbf2(l0, l1);
        }
    }
    __syncthreads();

    float acc[2][8][4];

    // ---- GEMM0: beta = sigmoid(sku @ Wb) -> half2 regs ---------------------
    mma_gemm(gWbHi, gWbLo, 4, smc, acc, tid, wid, tx);
    __half2 bh2[2][8][2];
#pragma unroll
    for (int mi = 0; mi < 2; mi++)
#pragma unroll
        for (int nb = 0; nb < 8; nb++) {
            bh2[mi][nb][0] = __floats2half2_rn(
                1.f / (1.f + expf(-acc[mi][nb][0])), 1.f / (1.f + expf(-acc[mi][nb][1])));
            bh2[mi][nb][1] = __floats2half2_rn(
                1.f / (1.f + expf(-acc[mi][nb][2])), 1.f / (1.f + expf(-acc[mi][nb][3])));
        }
    __syncthreads();   // X(sku) reads done

    // ---- stage 1: features -> X images -------------------------------------
#pragma unroll
    for (int tt = 0; tt < 2; tt++) {
        int h = wid + 8 * tt;          // warp-uniform
        float t = inputs[(size_t)(b0 + tx) * H + h];
        float f[C], e[C];
        float mu = 0.f;
#pragma unroll
        for (int c = 0; c < C; c++) {
            float cp = __shfl_sync(FULL, cps_r[tt], c);
            f[c] = fmaxf(t - cp, 0.f); mu += f[c];
        }
        mu *= (1.0f / C);
        float var = 0.f;
#pragma unroll
        for (int c = 0; c < C; c++) { float d = f[c] - mu; var = fmaf(d, d, var); }
        var *= (1.0f / C);
        float rs = rsqrtf(var + LN_EPS);
        float aw = __ldg(attn_w + h) * TEMP_INV;
        float m = -3.4e38f;
#pragma unroll
        for (int c = 0; c < C; c++) {
            float n = fmaf((f[c] - mu) * rs, __ldg(ln_gamma + h * C + c),
                           __ldg(ln_beta + h * C + c));
            f[c] = n;
            m = fmaxf(m, n * aw);
        }
        float s = 0.f;
#pragma unroll
        for (int c = 0; c < C; c++) { e[c] = expf(f[c] * aw - m); s += e[c]; }
        float inv = 1.0f / s;
        ull hid2[16];
#pragma unroll
        for (int d = 0; d < 16; d++) hid2[d] = 0ull;
#pragma unroll
        for (int c = 0; c < C; c++) {
            float a = f[c] * e[c] * inv;
            ull a2 = pack2(a, a);
            const ull* wr = reinterpret_cast<const ull*>(Wh + (h * C + c) * C);
#pragma unroll
            for (int d = 0; d < 16; d++) ffma2(hid2[d], a2, wr[d]);
        }
#pragma unroll
        for (int d = 0; d < 16; d++) {
            float2 hv = unpack2(hid2[d]);
            float v0 = mishf(hv.x), v1 = mishf(hv.y);
            __nv_bfloat16 h0 = __float2bfloat16(v0), h1 = __float2bfloat16(v1);
            uint32_t off = tx * XSTR + (h * 32 + 2 * d) * 2;
            __nv_bfloat162 hv2(h0, h1);
            *(uint32_t*)(smc + OFF_XHI + off) = *reinterpret_cast<uint32_t*>(&hv2);
            *(uint32_t*)(smc + OFF_XLO + off) =
                packbf2(v0 - __bfloat162float(h0), v1 - __bfloat162float(h1));
        }
    }
    __syncthreads();

    // ---- GEMM1: H1 = mish(X @ Wah) -----------------------------------------
    mma_gemm(gWahHi, gWahLo, 32, smc, acc, tid, wid, tx);
    __syncthreads();   // all warps done reading X
#pragma unroll
    for (int mi = 0; mi < 2; mi++)
#pragma unroll
        for (int nb = 0; nb < 8; nb++)
#pragma unroll
            for (int rb = 0; rb < 2; rb++) {
                int row = mi * 16 + rb * 8 + gq;
                int n = wn0 + nb * 8 + 2 * tg;
                float v0 = mishf(acc[mi][nb][rb * 2]);
                float v1 = mishf(acc[mi][nb][rb * 2 + 1]);
                __nv_bfloat16 h0 = __float2bfloat16(v0), h1 = __float2bfloat16(v1);
                uint32_t off = row * XSTR + n * 2;
                __nv_bfloat162 hv2(h0, h1);
                *(uint32_t*)(smc + OFF_XHI + off) = *reinterpret_cast<uint32_t*>(&hv2);
                *(uint32_t*)(smc + OFF_XLO + off) =
                    packbf2(v0 - __bfloat162float(h0), v1 - __bfloat162float(h1));
            }
    __syncthreads();

    // ---- GEMM2: logits = H1 @ Waa ------------------------------------------
    mma_gemm(gWaaHi, gWaaLo, 32, smc, acc, tid, wid, tx);

    // ---- epilogue -----------------------------------------------------------
    // per-thread rows: mi*16 + rb*8 + gq
    float mx[4] = {-3.4e38f, -3.4e38f, -3.4e38f, -3.4e38f};
#pragma unroll
    for (int mi = 0; mi < 2; mi++)
#pragma unroll
        for (int nb = 0; nb < 8; nb++)
#pragma unroll
            for (int rb = 0; rb < 2; rb++)
                mx[mi * 2 + rb] = fmaxf(mx[mi * 2 + rb],
                    fmaxf(acc[mi][nb][rb * 2], acc[mi][nb][rb * 2 + 1]));
#pragma unroll
    for (int q = 0; q < 4; q++) {
        mx[q] = fmaxf(mx[q], __shfl_xor_sync(FULL, mx[q], 1));
        mx[q] = fmaxf(mx[q], __shfl_xor_sync(FULL, mx[q], 2));
    }
    if (tg == 0) {
#pragma unroll
        for (int q = 0; q < 4; q++)
            ps0[wid * 32 + (q >> 1) * 16 + (q & 1) * 8 + gq] = mx[q];
    }
    __syncthreads();
    if (tid < 32) {
        float m = -3.4e38f;
#pragma unroll
        for (int w = 0; w < 8; w++) m = fmaxf(m, ps0[w * 32 + tid]);
        gmaxA[tid] = m;
    }
    __syncthreads();

    float sv[4] = {0.f, 0.f, 0.f, 0.f}, dv[4] = {0.f, 0.f, 0.f, 0.f};
#pragma unroll
    for (int mi = 0; mi < 2; mi++)
#pragma unroll
        for (int rb = 0; rb < 2; rb++) {
            int row = mi * 16 + rb * 8 + gq;
            float gm = gmaxA[row];
            float s = 0.f, d = 0.f;
#pragma unroll
            for (int nb = 0; nb < 8; nb++) {
                int n = wn0 + nb * 8 + 2 * tg;
                float e0 = expf((acc[mi][nb][rb * 2]     - gm) * TEMP_INV);
                float e1 = expf((acc[mi][nb][rb * 2 + 1] - gm) * TEMP_INV);
                uint32_t off = row * XSTR + n * 2;
                float2 hh = unbf2(*(const uint32_t*)(smc + OFF_XHI + off));
                float2 hl = unbf2(*(const uint32_t*)(smc + OFF_XLO + off));
                float h0 = hh.x + hl.x, h1 = hh.y + hl.y;
                float2 bb = __half22float2(bh2[mi][nb][rb]);
                float2 wo = *(const float2*)(sWo + n);
                s += e0 + e1;
                d = fmaf(e0 * h0 * bb.x, wo.x, d);
                d = fmaf(e1 * h1 * bb.y, wo.y, d);
            }
            sv[mi * 2 + rb] = s; dv[mi * 2 + rb] = d;
        }
#pragma unroll
    for (int q = 0; q < 4; q++) {
        sv[q] += __shfl_xor_sync(FULL, sv[q], 1);
        sv[q] += __shfl_xor_sync(FULL, sv[q], 2);
        dv[q] += __shfl_xor_sync(FULL, dv[q], 1);
        dv[q] += __shfl_xor_sync(FULL, dv[q], 2);
    }
    if (tg == 0) {
#pragma unroll
        for (int q = 0; q < 4; q++) {
            int row = (q >> 1) * 16 + (q & 1) * 8 + gq;
            ps0[wid * 32 + row] = sv[q];
            ps1[wid * 32 + row] = dv[q];
        }
    }
    __syncthreads();
    if (tid < 32) {
        float S = 0.f, D = 0.f;
#pragma unroll
        for (int w = 0; w < 8; w++) { S += ps0[w * 32 + tid]; D += ps1[w * 32 + tid]; }
        float alpha = 0.f;
        const float4* sk4 = (const float4*)(sku + (size_t)(b0 + tid) * SKUD);
#pragma unroll
        for (int q = 0; q < 16; q++) {
            float4 s4 = sk4[q];
            alpha += s4.x * sWaWo[4 * q]     + s4.y * sWaWo[4 * q + 1]
                   + s4.z * sWaWo[4 * q + 2] + s4.w * sWaWo[4 * q + 3];
        }
        out[b0 + tid] = D / S + alpha;
    }
}

extern "C" void kernel_launch(void* const* d_in, const int* in_sizes, int n_in,
                              void* d_out, int out_size)
{
    const float* inputs   = (const float*)d_in[0];
    const float* sku      = (const float*)d_in[1];
    const float* deltas   = (const float*)d_in[2];
    const float* ln_gamma = (const float*)d_in[3];
    const float* ln_beta  = (const float*)d_in[4];
    const float* attn_w   = (const float*)d_in[5];
    const float* Wh       = (const float*)d_in[6];
    const float* Wah      = (const float*)d_in[7];
    const float* Waa      = (const float*)d_in[8];
    const float* Wb       = (const float*)d_in[9];
    const float* Wa       = (const float*)d_in[10];
    const float* Wo       = (const float*)d_in[11];
    float* out = (float*)d_out;

    int B = in_sizes[0] / H;
    prep_kernel<<<1088, 256>>>(Wah, Waa, Wb);
    cudaFuncSetAttribute(holiday_mma_kernel,
                         cudaFuncAttributeMaxDynamicSharedMemorySize, SMEM_BYTES);
    holiday_mma_kernel<<<B / ROWS, NTHR, SMEM_BYTES>>>(
        inputs, sku, deltas, ln_gamma, ln_beta, attn_w, Wh, Wa, Wo, out);
}

// round 12
// speedup vs baseline: 3.5248x; 1.6110x over previous
#include <cuda_runtime.h>
#include <cuda_fp16.h>
#include <cuda_bf16.h>
#include <math.h>
#include <stdint.h>

// prep-built weight images in B-fragment order: idx = ((kb*64+nb)*32+lane)*2+reg
__device__ __align__(16) uint32_t gWahHi[131072];
__device__ __align__(16) uint32_t gWahLo[131072];
__device__ __align__(16) uint32_t gWaaHi[131072];
__device__ __align__(16) uint32_t gWaaLo[131072];
__device__ __align__(16) uint32_t gWbHi [16384];
__device__ __align__(16) uint32_t gWbLo [16384];

namespace {
constexpr int H = 16, C = 32, HID = 512, SKUD = 64, ROWS = 32, NTHR = 512;
constexpr float TEMP_INV = 1.0f / 0.7f, TMAX = 365.0f, LN_EPS = 1e-3f;
constexpr int XSTR = 1040;                 // X image row stride in bytes (520 bf16)
// smem byte offsets
constexpr int OFF_XHI = 0;                 // 32*1040 = 33280
constexpr int OFF_XLO = 33280;
constexpr int OFF_WO  = 66560;             // 512 f32
constexpr int OFF_PS0 = 68608;             // 16*32 f32
constexpr int OFF_PS1 = 70656;             // 16*32 f32
constexpr int OFF_GMX = 72704;             // 32 f32
constexpr int OFF_WAWO= 72832;             // 64 f32
constexpr int SMEM_BYTES = 73088;
}

using ull = unsigned long long;

__device__ __forceinline__ ull pack2(float x, float y) {
    ull r; asm("mov.b64 %0, {%1, %2};" : "=l"(r) : "f"(x), "f"(y)); return r;
}
__device__ __forceinline__ float2 unpack2(ull v) {
    float2 f; asm("mov.b64 {%0, %1}, %2;" : "=f"(f.x), "=f"(f.y) : "l"(v)); return f;
}
__device__ __forceinline__ void ffma2(ull& d, ull a, ull b) {
    asm("fma.rn.f32x2 %0, %1, %2, %0;" : "+l"(d) : "l"(a), "l"(b));
}
__device__ __forceinline__ float mishf(float x) {
    float sp = (x > 20.f) ? x : log1pf(expf(x));
    return x * tanhf(sp);
}
__device__ __forceinline__ uint32_t packbf2(float a, float b) {
    __nv_bfloat162 v = __floats2bfloat162_rn(a, b);
    return *reinterpret_cast<uint32_t*>(&v);
}
__device__ __forceinline__ float2 unbf2(uint32_t u) {
    __nv_bfloat162 v = *reinterpret_cast<__nv_bfloat162*>(&u);
    return make_float2(__bfloat162float(v.x), __bfloat162float(v.y));
}
__device__ __forceinline__ void hmma(float* acc, uint32_t a0, uint32_t a1,
                                     uint32_t a2, uint32_t a3, uint32_t b0, uint32_t b1) {
    asm volatile("mma.sync.aligned.m16n8k16.row.col.f32.bf16.bf16.f32 "
        "{%0,%1,%2,%3}, {%4,%5,%6,%7}, {%8,%9}, {%0,%1,%2,%3};"
        : "+f"(acc[0]), "+f"(acc[1]), "+f"(acc[2]), "+f"(acc[3])
        : "r"(a0), "r"(a1), "r"(a2), "r"(a3), "r"(b0), "r"(b1));
}

// split-bf16 MMA GEMM, barrier-free. Warp tile 32 rows x 32 cols.
// acc[mi][nb][4]; A from smem X images, B frag-order from global (L2),
// register double-buffered across kb.
__device__ __forceinline__ void mma_gemm(
    const uint32_t* __restrict__ gHi, const uint32_t* __restrict__ gLo,
    int nk, const char* smc, float acc[2][4][4], int wid, int tx)
{
#pragma unroll
    for (int mi = 0; mi < 2; mi++)
#pragma unroll
        for (int nb = 0; nb < 4; nb++)
#pragma unroll
            for (int e = 0; e < 4; e++) acc[mi][nb][e] = 0.f;

    const int tg = tx & 3, gq = tx >> 2;
    const ull* pH = (const ull*)gHi;
    const ull* pL = (const ull*)gLo;
    const int base0 = (wid * 4) * 32 + tx;

    ull bh[2][4], bl[2][4];
#pragma unroll
    for (int nb = 0; nb < 4; nb++) {
        bh[0][nb] = __ldg(pH + base0 + nb * 32);
        bl[0][nb] = __ldg(pL + base0 + nb * 32);
    }
#pragma unroll 2
    for (int kb = 0; kb < nk; kb++) {
        int cur = kb & 1, nxt = cur ^ 1;
        if (kb + 1 < nk) {
            int nb0 = (kb + 1) * 2048 + base0;
#pragma unroll
            for (int nb = 0; nb < 4; nb++) {
                bh[nxt][nb] = __ldg(pH + nb0 + nb * 32);
                bl[nxt][nb] = __ldg(pL + nb0 + nb * 32);
            }
        }
        uint32_t ah[2][4], al[2][4];
#pragma unroll
        for (int mi = 0; mi < 2; mi++) {
            int base = (mi * 16 + gq) * XSTR + kb * 32 + 4 * tg;
            ah[mi][0] = *(const uint32_t*)(smc + OFF_XHI + base);
            ah[mi][1] = *(const uint32_t*)(smc + OFF_XHI + base + 8 * XSTR);
            ah[mi][2] = *(const uint32_t*)(smc + OFF_XHI + base + 16);
            ah[mi][3] = *(const uint32_t*)(smc + OFF_XHI + base + 8 * XSTR + 16);
            al[mi][0] = *(const uint32_t*)(smc + OFF_XLO + base);
            al[mi][1] = *(const uint32_t*)(smc + OFF_XLO + base + 8 * XSTR);
            al[mi][2] = *(const uint32_t*)(smc + OFF_XLO + base + 16);
            al[mi][3] = *(const uint32_t*)(smc + OFF_XLO + base + 8 * XSTR + 16);
        }
#pragma unroll
        for (int nb = 0; nb < 4; nb++) {
            uint32_t bh0 = (uint32_t)bh[cur][nb], bh1 = (uint32_t)(bh[cur][nb] >> 32);
            uint32_t bl0 = (uint32_t)bl[cur][nb], bl1 = (uint32_t)(bl[cur][nb] >> 32);
#pragma unroll
            for (int mi = 0; mi < 2; mi++) {
                hmma(acc[mi][nb], ah[mi][0], ah[mi][1], ah[mi][2], ah[mi][3], bh0, bh1);
                hmma(acc[mi][nb], ah[mi][0], ah[mi][1], ah[mi][2], ah[mi][3], bl0, bl1);
                hmma(acc[mi][nb], al[mi][0], al[mi][1], al[mi][2], al[mi][3], bh0, bh1);
            }
        }
    }
}

// ---------- prep: build frag-order bf16 hi/lo weight images ------------------
__global__ void prep_kernel(const float* __restrict__ Wah,
                            const float* __restrict__ Waa,
                            const float* __restrict__ Wb)
{
    int gid = blockIdx.x * 256 + threadIdx.x;
    const float* W; uint32_t *dHi, *dLo; int idx;
    if (gid < 131072)      { W = Wah; dHi = gWahHi; dLo = gWahLo; idx = gid; }
    else if (gid < 262144) { W = Waa; dHi = gWaaHi; dLo = gWaaLo; idx = gid - 131072; }
    else                   { W = Wb;  dHi = gWbHi;  dLo = gWbLo;  idx = gid - 262144; }
    int reg = idx & 1, lane = (idx >> 1) & 31, nb = (idx >> 6) & 63, kb = idx >> 12;
    int tg = lane & 3, gq = lane >> 2;
    int k0 = kb * 16 + 2 * tg + reg * 8;
    int n  = nb * 8 + gq;
    float w0 = W[(size_t)k0 * 512 + n];
    float w1 = W[(size_t)(k0 + 1) * 512 + n];
    __nv_bfloat16 h0 = __float2bfloat16(w0), h1 = __float2bfloat16(w1);
    float l0f = w0 - __bfloat162float(h0), l1f = w1 - __bfloat162float(h1);
    __nv_bfloat162 hv(h0, h1);
    __nv_bfloat162 lv(__float2bfloat16(l0f), __float2bfloat16(l1f));
    dHi[idx] = *reinterpret_cast<uint32_t*>(&hv);
    dLo[idx] = *reinterpret_cast<uint32_t*>(&lv);
}

__global__ __launch_bounds__(NTHR)
void holiday_mma_kernel(
    const float* __restrict__ inputs, const float* __restrict__ sku,
    const float* __restrict__ deltas, const float* __restrict__ ln_gamma,
    const float* __restrict__ ln_beta, const float* __restrict__ attn_w,
    const float* __restrict__ Wh, const float* __restrict__ Wa,
    const float* __restrict__ Wo, float* __restrict__ out)
{
    extern __shared__ char smc[];
    float* sWo   = (float*)(smc + OFF_WO);
    float* ps0   = (float*)(smc + OFF_PS0);
    float* ps1   = (float*)(smc + OFF_PS1);
    float* gmaxA = (float*)(smc + OFF_GMX);
    float* sWaWo = (float*)(smc + OFF_WAWO);

    const int tid = threadIdx.x, tx = tid & 31, wid = tid >> 5;   // 16 warps
    const int tg = tx & 3, gq = tx >> 2;
    const int wn0 = wid * 32;
    const int b0 = blockIdx.x * ROWS;
    const unsigned FULL = 0xffffffffu;

    // ---- prologue: Wo, alpha fold, changepoints ----------------------------
    for (int i = tid; i < HID; i += NTHR) sWo[i] = Wo[i];
#pragma unroll
    for (int si = 0; si < 4; si++) {
        int s = wid * 4 + si;
        float p = 0.f;
#pragma unroll
        for (int j = 0; j < 16; j++) {
            int c = tx + 32 * j;
            p = fmaf(__ldg(Wa + s * HID + c), __ldg(Wo + c), p);
        }
#pragma unroll
        for (int o = 16; o > 0; o >>= 1) p += __shfl_xor_sync(FULL, p, o);
        if (tx == 0) sWaWo[s] = p;
    }
    float cps_r;
    {
        float d  = deltas[wid * C + tx];
        float sp = (d > 20.f) ? d : log1pf(expf(d));
        float s  = sp;
#pragma unroll
        for (int o = 1; o < 32; o <<= 1) {
            float v = __shfl_up_sync(FULL, s, o);
            if (tx >= o) s += v;
        }
        cps_r = s * (TMAX / __shfl_sync(FULL, s, 31));
    }

    // ---- stage sku into X images (rows 0..31, k 0..63) ---------------------
    {
        int r = tid >> 4, k0 = (tid & 15) * 4;
        float4 a = *(const float4*)(sku + (size_t)(b0 + r) * SKUD + k0);
        float v[4] = {a.x, a.y, a.z, a.w};
#pragma unroll
        for (int e = 0; e < 2; e++) {
            float v0 = v[2 * e], v1 = v[2 * e + 1];
            __nv_bfloat16 h0 = __float2bfloat16(v0), h1 = __float2bfloat16(v1);
            uint32_t off = r * XSTR + (k0 + 2 * e) * 2;
            __nv_bfloat162 hv2(h0, h1);
            *(uint32_t*)(smc + OFF_XHI + off) = *reinterpret_cast<uint32_t*>(&hv2);
            *(uint32_t*)(smc + OFF_XLO + off) =
                packbf2(v0 - __bfloat162float(h0), v1 - __bfloat162float(h1));
        }
    }
    __syncthreads();

    float acc[2][4][4];

    // ---- GEMM0: beta = sigmoid(sku @ Wb) -> half2 regs ---------------------
    mma_gemm(gWbHi, gWbLo, 4, smc, acc, wid, tx);
    __half2 bh2[2][4][2];
#pragma unroll
    for (int mi = 0; mi < 2; mi++)
#pragma unroll
        for (int nb = 0; nb < 4; nb++) {
            bh2[mi][nb][0] = __floats2half2_rn(
                1.f / (1.f + expf(-acc[mi][nb][0])), 1.f / (1.f + expf(-acc[mi][nb][1])));
            bh2[mi][nb][1] = __floats2half2_rn(
                1.f / (1.f + expf(-acc[mi][nb][2])), 1.f / (1.f + expf(-acc[mi][nb][3])));
        }
    __syncthreads();   // all GEMM0 A-reads done -> stage1 may overwrite X

    // ---- stage 1: features -> X images (h = wid, r = tx) -------------------
    {
        int h = wid;
        float t = inputs[(size_t)(b0 + tx) * H + h];
        float f[C], e[C];
        float mu = 0.f;
#pragma unroll
        for (int c = 0; c < C; c++) {
            float cp = __shfl_sync(FULL, cps_r, c);
            f[c] = fmaxf(t - cp, 0.f); mu += f[c];
        }
        mu *= (1.0f / C);
        float var = 0.f;
#pragma unroll
        for (int c = 0; c < C; c++) { float d = f[c] - mu; var = fmaf(d, d, var); }
        var *= (1.0f / C);
        float rs = rsqrtf(var + LN_EPS);
        float aw = __ldg(attn_w + h) * TEMP_INV;
        float m = -3.4e38f;
#pragma unroll
        for (int c = 0; c < C; c++) {
            float n = fmaf((f[c] - mu) * rs, __ldg(ln_gamma + h * C + c),
                           __ldg(ln_beta + h * C + c));
            f[c] = n;
            m = fmaxf(m, n * aw);
        }
        float s = 0.f;
#pragma unroll
        for (int c = 0; c < C; c++) { e[c] = expf(f[c] * aw - m); s += e[c]; }
        float inv = 1.0f / s;
        ull hid2[16];
#pragma unroll
        for (int d = 0; d < 16; d++) hid2[d] = 0ull;
#pragma unroll
        for (int c = 0; c < C; c++) {
            float a = f[c] * e[c] * inv;
            ull a2 = pack2(a, a);
            const ull* wr = reinterpret_cast<const ull*>(Wh + (h * C + c) * C);
#pragma unroll
            for (int d = 0; d < 16; d++) ffma2(hid2[d], a2, wr[d]);
        }
#pragma unroll
        for (int d = 0; d < 16; d++) {
            float2 hv = unpack2(hid2[d]);
            float v0 = mishf(hv.x), v1 = mishf(hv.y);
            __nv_bfloat16 h0 = __float2bfloat16(v0), h1 = __float2bfloat16(v1);
            uint32_t off = tx * XSTR + (h * 32 + 2 * d) * 2;
            __nv_bfloat162 hv2(h0, h1);
            *(uint32_t*)(smc + OFF_XHI + off) = *reinterpret_cast<uint32_t*>(&hv2);
            *(uint32_t*)(smc + OFF_XLO + off) =
                packbf2(v0 - __bfloat162float(h0), v1 - __bfloat162float(h1));
        }
    }
    __syncthreads();

    // ---- GEMM1: H1 = mish(X @ Wah) -----------------------------------------
    mma_gemm(gWahHi, gWahLo, 32, smc, acc, wid, tx);
    __syncthreads();   // all X reads done -> overwrite with H1
#pragma unroll
    for (int mi = 0; mi < 2; mi++)
#pragma unroll
        for (int nb = 0; nb < 4; nb++)
#pragma unroll
            for (int rb = 0; rb < 2; rb++) {
                int row = mi * 16 + rb * 8 + gq;
                int n = wn0 + nb * 8 + 2 * tg;
                float v0 = mishf(acc[mi][nb][rb * 2]);
                float v1 = mishf(acc[mi][nb][rb * 2 + 1]);
                __nv_bfloat16 h0 = __float2bfloat16(v0), h1 = __float2bfloat16(v1);
                uint32_t off = row * XSTR + n * 2;
                __nv_bfloat162 hv2(h0, h1);
                *(uint32_t*)(smc + OFF_XHI + off) = *reinterpret_cast<uint32_t*>(&hv2);
                *(uint32_t*)(smc + OFF_XLO + off) =
                    packbf2(v0 - __bfloat162float(h0), v1 - __bfloat162float(h1));
            }
    __syncthreads();

    // ---- GEMM2: logits = H1 @ Waa ------------------------------------------
    mma_gemm(gWaaHi, gWaaLo, 32, smc, acc, wid, tx);

    // ---- epilogue -----------------------------------------------------------
    float mx[4] = {-3.4e38f, -3.4e38f, -3.4e38f, -3.4e38f};
#pragma unroll
    for (int mi = 0; mi < 2; mi++)
#pragma unroll
        for (int nb = 0; nb < 4; nb++)
#pragma unroll
            for (int rb = 0; rb < 2; rb++)
                mx[mi * 2 + rb] = fmaxf(mx[mi * 2 + rb],
                    fmaxf(acc[mi][nb][rb * 2], acc[mi][nb][rb * 2 + 1]));
#pragma unroll
    for (int q = 0; q < 4; q++) {
        mx[q] = fmaxf(mx[q], __shfl_xor_sync(FULL, mx[q], 1));
        mx[q] = fmaxf(mx[q], __shfl_xor_sync(FULL, mx[q], 2));
    }
    if (tg == 0) {
#pragma unroll
        for (int q = 0; q < 4; q++)
            ps0[wid * 32 + (q >> 1) * 16 + (q & 1) * 8 + gq] = mx[q];
    }
    __syncthreads();
    if (tid < 32) {
        float m = -3.4e38f;
#pragma unroll
        for (int w = 0; w < 16; w++) m = fmaxf(m, ps0[w * 32 + tid]);
        gmaxA[tid] = m;
    }
    __syncthreads();

    float sv[4] = {0.f, 0.f, 0.f, 0.f}, dv[4] = {0.f, 0.f, 0.f, 0.f};
#pragma unroll
    for (int mi = 0; mi < 2; mi++)
#pragma unroll
        for (int rb = 0; rb < 2; rb++) {
            int row = mi * 16 + rb * 8 + gq;
            float gm = gmaxA[row];
            float s = 0.f, d = 0.f;
#pragma unroll
            for (int nb = 0; nb < 4; nb++) {
                int n = wn0 + nb * 8 + 2 * tg;
                float e0 = expf((acc[mi][nb][rb * 2]     - gm) * TEMP_INV);
                float e1 = expf((acc[mi][nb][rb * 2 + 1] - gm) * TEMP_INV);
                uint32_t off = row * XSTR + n * 2;
                float2 hh = unbf2(*(const uint32_t*)(smc + OFF_XHI + off));
                float2 hl = unbf2(*(const uint32_t*)(smc + OFF_XLO + off));
                float h0 = hh.x + hl.x, h1 = hh.y + hl.y;
                float2 bb = __half22float2(bh2[mi][nb][rb]);
                float2 wo = *(const float2*)(sWo + n);
                s += e0 + e1;
                d = fmaf(e0 * h0 * bb.x, wo.x, d);
                d = fmaf(e1 * h1 * bb.y, wo.y, d);
            }
            sv[mi * 2 + rb] = s; dv[mi * 2 + rb] = d;
        }
#pragma unroll
    for (int q = 0; q < 4; q++) {
        sv[q] += __shfl_xor_sync(FULL, sv[q], 1);
        sv[q] += __shfl_xor_sync(FULL, sv[q], 2);
        dv[q] += __shfl_xor_sync(FULL, dv[q], 1);
        dv[q] += __shfl_xor_sync(FULL, dv[q], 2);
    }
    if (tg == 0) {
#pragma unroll
        for (int q = 0; q < 4; q++) {
            int row = (q >> 1) * 16 + (q & 1) * 8 + gq;
            ps0[wid * 32 + row] = sv[q];
            ps1[wid * 32 + row] = dv[q];
        }
    }
    __syncthreads();
    if (tid < 32) {
        float S = 0.f, D = 0.f;
#pragma unroll
        for (int w = 0; w < 16; w++) { S += ps0[w * 32 + tid]; D += ps1[w * 32 + tid]; }
        float alpha = 0.f;
        const float4* sk4 = (const float4*)(sku + (size_t)(b0 + tid) * SKUD);
#pragma unroll
        for (int q = 0; q < 16; q++) {
            float4 s4 = sk4[q];
            alpha += s4.x * sWaWo[4 * q]     + s4.y * sWaWo[4 * q + 1]
                   + s4.z * sWaWo[4 * q + 2] + s4.w * sWaWo[4 * q + 3];
        }
        out[b0 + tid] = D / S + alpha;
    }
}

extern "C" void kernel_launch(void* const* d_in, const int* in_sizes, int n_in,
                              void* d_out, int out_size)
{
    const float* inputs   = (const float*)d_in[0];
    const float* sku      = (const float*)d_in[1];
    const float* deltas   = (const float*)d_in[2];
    const float* ln_gamma = (const float*)d_in[3];
    const float* ln_beta  = (const float*)d_in[4];
    const float* attn_w   = (const float*)d_in[5];
    const float* Wh       = (const float*)d_in[6];
    const float* Wah      = (const float*)d_in[7];
    const float* Waa      = (const float*)d_in[8];
    const float* Wb       = (const float*)d_in[9];
    const float* Wa       = (const float*)d_in[10];
    const float* Wo       = (const float*)d_in[11];
    float* out = (float*)d_out;

    int B = in_sizes[0] / H;
    prep_kernel<<<1088, 256>>>(Wah, Waa, Wb);
    cudaFuncSetAttribute(holiday_mma_kernel,
                         cudaFuncAttributeMaxDynamicSharedMemorySize, SMEM_BYTES);
    holiday_mma_kernel<<<B / ROWS, NTHR, SMEM_BYTES>>>(
        inputs, sku, deltas, ln_gamma, ln_beta, attn_w, Wh, Wa, Wo, out);
}